// round 1
// baseline (speedup 1.0000x reference)
#include <cuda_runtime.h>
#include <math.h>

#define NFRAMES   16384
#define HOPC      240
#define HOP2XC    480
#define L2X       (NFRAMES*HOP2XC)      /* 7,864,320 */
#define NSTFT     (NFRAMES+1)           /* 16385 */
#define OUTLEN    (NFRAMES*HOPC)        /* 3,932,160 */
#define PI_D      3.14159265358979323846

// ---------------- static device scratch (no runtime allocation) ----------------
__device__ float  g_p2x[L2X];                 // 31.5 MB  (2x-rate excitation)
__device__ float  g_ybuf[NSTFT * 512];        // 33.6 MB  (per-frame windowed istft output)
__device__ double g_a[NFRAMES];               // f0or1
__device__ double g_b[NFRAMES];               // f1or0
__device__ double g_S[NFRAMES];               // per-frame phase increment sum
__device__ double g_base[NFRAMES];            // exclusive prefix (mod 1)
__device__ unsigned char g_vuv[NFRAMES + 1];  // 3 band bits per frame
__device__ float  g_w1024[1024];
__device__ float  g_w512[512];
__device__ float2 g_tw[512];                  // e^{-2*pi*i*k/1024}
__device__ float  g_trans[HOP2XC];            // sin^2 crossfade

// ---------------- small helpers ----------------
__device__ __forceinline__ float2 cmul(float2 a, float2 b) {
    return make_float2(a.x * b.x - a.y * b.y, a.x * b.y + a.y * b.x);
}
__device__ __forceinline__ float2 cadd(float2 a, float2 b) { return make_float2(a.x + b.x, a.y + b.y); }
__device__ __forceinline__ float2 csub(float2 a, float2 b) { return make_float2(a.x - b.x, a.y - b.y); }

// ---------------- K0: tables ----------------
__global__ void k_setup() {
    int t = threadIdx.x;  // 1024 threads
    if (t < 1024) g_w1024[t] = (float)(0.5 - 0.5 * cos(2.0 * PI_D * (double)t / 1024.0));
    if (t < 512) {
        g_w512[t] = (float)(0.5 - 0.5 * cos(2.0 * PI_D * (double)t / 512.0));
        double ang = -2.0 * PI_D * (double)t / 1024.0;
        g_tw[t] = make_float2((float)cos(ang), (float)sin(ang));
    }
    if (t < HOP2XC) {
        double s = sin(((double)t / (double)HOP2XC) * (PI_D * 0.5));
        g_trans[t] = (float)(s * s);
    }
}

// ---------------- K1: per-frame values ----------------
__global__ void k_frames(const float* __restrict__ f0) {
    int i = blockIdx.x * blockDim.x + threadIdx.x;
    if (i >= NFRAMES) return;
    double fi = (double)f0[i];
    double fn = (i + 1 < NFRAMES) ? (double)f0[i + 1] : 0.0;
    double a = (fi != 0.0) ? fi : fn;
    double b = (fn != 0.0) ? fn : fi;
    g_a[i] = a;
    g_b[i] = b;
    // sum_{j=0..479} (a + (b-a)*j/480)/96000  -- closed form matching per-sample formula at j=479
    g_S[i] = (480.0 * a + (b - a) * (114960.0 / 480.0)) / 96000.0;
    unsigned char m = 0;
    if (fi >= 500.0 && fi < 1500.0) m |= 1;                                  // py48 band
    if (fi >= (24000.0 / 144.0) && fi < 500.0) m |= 2;                        // py144 band
    if (fi >= (24000.0 / 432.0) && fi < (24000.0 / 144.0)) m |= 4;            // py432 band
    g_vuv[i] = m;
    if (i == NFRAMES - 1) g_vuv[NFRAMES] = 0;
}

// ---------------- K2: frame-level exclusive scan (mod 1), one block ----------------
__global__ void k_scan() {
    __shared__ double sh[256];
    const int t = threadIdx.x;           // 256 threads, 64 elems each
    const int b0 = t * 64;
    double s = 0.0;
    for (int j = 0; j < 64; j++) s += g_S[b0 + j];
    sh[t] = s;
    __syncthreads();
    // inclusive Hillis-Steele scan
    for (int off = 1; off < 256; off <<= 1) {
        double v = (t >= off) ? sh[t - off] : 0.0;
        __syncthreads();
        sh[t] += v;
        __syncthreads();
    }
    double base = (t > 0) ? sh[t - 1] : 0.0;
    for (int j = 0; j < 64; j++) {
        g_base[b0 + j] = fmod(base, 1.0);
        base += g_S[b0 + j];
    }
}

// ---------------- K3: excitation signal at 2x rate ----------------
__device__ __forceinline__ float band_lookup(const float* __restrict__ tab, int maxi,
                                             float phase, float tr, float v0, float v1) {
    if (v0 == 0.0f && v1 == 0.0f) return 0.0f;
    float mask = v0 + (v1 - v0) * tr;
    float idxf = phase * (float)maxi;
    idxf = fminf(fmaxf(idxf, 0.0f), (float)maxi);
    int lo = (int)floorf(idxf);
    float tt = idxf - (float)lo;
    int hi = min(lo + 1, maxi);
    float lv = __ldg(tab + lo);
    float hv = __ldg(tab + hi);
    return mask * (lv + (hv - lv) * tt);
}

__global__ void k_gen(const float* __restrict__ py48, const float* __restrict__ py144,
                      const float* __restrict__ py432) {
    const int i = blockIdx.x;       // frame
    const int j = threadIdx.x;      // 0..479
    const double a = g_a[i], b = g_b[i], base = g_base[i];
    const double f0c = a + (b - a) * ((double)j / 480.0);
    const double within = ((double)(j + 1) * a +
                           (b - a) * ((double)(j * (j + 1) / 2) / 480.0)) / 96000.0;
    const float phase = (float)fmod(base + within, 1.0);
    const float tr = g_trans[j];
    const unsigned vi = g_vuv[i], vn = g_vuv[i + 1];

    float acc = 0.0f;
    acc += band_lookup(py48, 48 * 1024, phase, tr, (float)(vi & 1), (float)(vn & 1));
    acc += band_lookup(py144, 144 * 1024, phase, tr, (float)((vi >> 1) & 1), (float)((vn >> 1) & 1));
    acc += band_lookup(py432, 432 * 1024, phase, tr, (float)((vi >> 2) & 1), (float)((vn >> 2) & 1));

    g_p2x[i * HOP2XC + j] = acc * (float)f0c / 48000.0f;
}

// ---------------- K4: per-frame 1024-pt FFT -> truncate -> 512-pt irfft -> *w512 ----------------
__global__ void __launch_bounds__(256) k_fft() {
    __shared__ float2 A[1024];
    __shared__ float2 C[512];
    const int tid = threadIdx.x;
    const int frame = blockIdx.x;

    // load with reflect padding, window, bit-reversed placement (10-bit)
    for (int n = tid; n < 1024; n += 256) {
        int g = frame * HOP2XC - 512 + n;
        if (g < 0) g = -g;
        if (g >= L2X) g = 2 * L2X - 2 - g;
        float x = g_p2x[g] * g_w1024[n];
        A[__brev((unsigned)n) >> 22] = make_float2(x, 0.0f);
    }
    __syncthreads();

    // forward 1024-pt radix-2 DIT
    #pragma unroll
    for (int s = 1; s <= 10; s++) {
        const int half = 1 << (s - 1);
        #pragma unroll
        for (int k = tid; k < 512; k += 256) {
            const int jj = k & (half - 1);
            const int p = ((k >> (s - 1)) << s) + jj;
            const float2 w = g_tw[jj << (10 - s)];
            const float2 u = A[p];
            const float2 v = cmul(A[p + half], w);
            A[p] = cadd(u, v);
            A[p + half] = csub(u, v);
        }
        __syncthreads();
    }

    // build conj(B) where B = Hermitian extension of X[0..256] with DC/Nyquist imag dropped.
    // write in 9-bit bit-reversed order for the inverse DIT.
    for (int k = tid; k < 512; k += 256) {
        float2 v;
        if (k == 0)        v = make_float2(A[0].x, 0.0f);
        else if (k < 256)  v = make_float2(A[k].x, -A[k].y);       // conj(X[k])
        else if (k == 256) v = make_float2(A[256].x, 0.0f);
        else               v = A[512 - k];                          // conj(conj(X[512-k]))
        C[__brev((unsigned)k) >> 23] = v;
    }
    __syncthreads();

    // 512-pt forward FFT of conj(B); y[m] = Re(...)/512
    #pragma unroll
    for (int s = 1; s <= 9; s++) {
        const int half = 1 << (s - 1);
        {
            const int k = tid;  // exactly 256 butterflies
            const int jj = k & (half - 1);
            const int p = ((k >> (s - 1)) << s) + jj;
            const float2 w = g_tw[jj << (10 - s)];  // e^{-2pi i jj / 2^s}
            const float2 u = C[p];
            const float2 v = cmul(C[p + half], w);
            C[p] = cadd(u, v);
            C[p + half] = csub(u, v);
        }
        __syncthreads();
    }

    for (int m = tid; m < 512; m += 256) {
        g_ybuf[frame * 512 + m] = C[m].x * (1.0f / 512.0f) * g_w512[m];
    }
}

// ---------------- K5: deterministic OLA gather + env normalize ----------------
__global__ void k_ola(float* __restrict__ out) {
    int n = blockIdx.x * blockDim.x + threadIdx.x;
    if (n >= OUTLEN) return;
    const int s = n + 256;                       // pad = 512/2
    int tlo = (s >= 512) ? (s - 511 + 239) / 240 : 0;
    int thi = s / 240;
    if (thi > NFRAMES) thi = NFRAMES;            // frames 0..16384
    float sig = 0.0f, env = 0.0f;
    for (int t = tlo; t <= thi; t++) {
        const int m = s - 240 * t;               // 0..511
        const float w = g_w512[m];
        sig += g_ybuf[t * 512 + m];
        env += w * w;
    }
    out[n] = (env > 1e-11f) ? (sig / env) : 0.0f;
}

// ---------------- launcher ----------------
extern "C" void kernel_launch(void* const* d_in, const int* in_sizes, int n_in,
                              void* d_out, int out_size) {
    const float* f0    = (const float*)d_in[0];
    const float* py48  = (const float*)d_in[1];
    const float* py144 = (const float*)d_in[2];
    const float* py432 = (const float*)d_in[3];
    float* out = (float*)d_out;
    (void)in_sizes; (void)n_in; (void)out_size;

    k_setup<<<1, 1024>>>();
    k_frames<<<(NFRAMES + 255) / 256, 256>>>(f0);
    k_scan<<<1, 256>>>();
    k_gen<<<NFRAMES, HOP2XC>>>(py48, py144, py432);
    k_fft<<<NSTFT, 256>>>();
    k_ola<<<(OUTLEN + 255) / 256, 256>>>(out);
}

// round 2
// speedup vs baseline: 2.3761x; 2.3761x over previous
#include <cuda_runtime.h>
#include <math.h>

#define NFRAMES   16384
#define HOPC      240
#define HOP2XC    480
#define L2X       (NFRAMES*HOP2XC)      /* 7,864,320 */
#define NSTFT     (NFRAMES+1)           /* 16385 */
#define OUTLEN    (NFRAMES*HOPC)        /* 3,932,160 */
#define PI_D      3.14159265358979323846

// ---------------- static device scratch ----------------
__device__ float  g_p2x[L2X];                 // 2x-rate excitation
__device__ float  g_ybuf[NSTFT * 512];        // per-frame windowed istft contribution
__device__ double g_S[NFRAMES];               // per-frame phase increment
__device__ double g_base[NFRAMES];            // exclusive prefix mod 1
__device__ double g_c1[NFRAMES];              // a/96000
__device__ double g_c2h[NFRAMES];             // (b-a)/(2*480*96000)
__device__ float  g_af[NFRAMES];
__device__ float  g_bf[NFRAMES];
__device__ unsigned char g_vuv[NFRAMES + 1];
__device__ float  g_w1024[1024];
__device__ float  g_w512[512];
__device__ float2 g_tw[1024];                 // exp(-2*pi*i*k/1024), full circle
__device__ float  g_trans[HOP2XC];

// ---------------- helpers ----------------
__device__ __forceinline__ float2 cmul(float2 a, float2 b) {
    return make_float2(a.x * b.x - a.y * b.y, a.x * b.y + a.y * b.x);
}
__device__ __forceinline__ float2 cadd(float2 a, float2 b) { return make_float2(a.x + b.x, a.y + b.y); }
__device__ __forceinline__ float2 csub(float2 a, float2 b) { return make_float2(a.x - b.x, a.y - b.y); }

#define PADI(i) ((i) + ((i) >> 4))   /* pad every 16 float2 to spread banks */
#define PADSZ   (512 + 32)

// ---------------- K0: tables ----------------
__global__ void k_setup() {
    int t = threadIdx.x;  // 1024 threads
    g_w1024[t] = (float)(0.5 - 0.5 * cos(2.0 * PI_D * (double)t / 1024.0));
    double ang = -2.0 * PI_D * (double)t / 1024.0;
    g_tw[t] = make_float2((float)cos(ang), (float)sin(ang));
    if (t < 512) g_w512[t] = (float)(0.5 - 0.5 * cos(2.0 * PI_D * (double)t / 512.0));
    if (t < HOP2XC) {
        double s = sin(((double)t / (double)HOP2XC) * (PI_D * 0.5));
        g_trans[t] = (float)(s * s);
    }
}

// ---------------- K1: per-frame values ----------------
__global__ void k_frames(const float* __restrict__ f0) {
    int i = blockIdx.x * blockDim.x + threadIdx.x;
    if (i >= NFRAMES) return;
    double fi = (double)f0[i];
    double fn = (i + 1 < NFRAMES) ? (double)f0[i + 1] : 0.0;
    double a = (fi != 0.0) ? fi : fn;
    double b = (fn != 0.0) ? fn : fi;
    g_af[i] = (float)a;
    g_bf[i] = (float)b;
    g_c1[i] = a / 96000.0;
    g_c2h[i] = (b - a) / (2.0 * 480.0 * 96000.0);
    g_S[i] = (480.0 * a + (b - a) * (114960.0 / 480.0)) / 96000.0;
    unsigned char m = 0;
    if (fi >= 500.0 && fi < 1500.0) m |= 1;
    if (fi >= (24000.0 / 144.0) && fi < 500.0) m |= 2;
    if (fi >= (24000.0 / 432.0) && fi < (24000.0 / 144.0)) m |= 4;
    g_vuv[i] = m;
    if (i == NFRAMES - 1) g_vuv[NFRAMES] = 0;
}

// ---------------- K2: frame-level scan (mod 1), one block ----------------
__global__ void k_scan() {
    __shared__ double sh[256];
    const int t = threadIdx.x;
    const int b0 = t * 64;
    double s = 0.0;
    for (int j = 0; j < 64; j++) s += g_S[b0 + j];
    sh[t] = s;
    __syncthreads();
    for (int off = 1; off < 256; off <<= 1) {
        double v = (t >= off) ? sh[t - off] : 0.0;
        __syncthreads();
        sh[t] += v;
        __syncthreads();
    }
    double base = (t > 0) ? sh[t - 1] : 0.0;
    for (int j = 0; j < 64; j++) {
        g_base[b0 + j] = fmod(base, 1.0);
        base += g_S[b0 + j];
    }
}

// ---------------- K3: excitation at 2x rate ----------------
__device__ __forceinline__ float band_lookup(const float* __restrict__ tab, int maxi,
                                             float phase, float tr, float v0, float v1) {
    if (v0 == 0.0f && v1 == 0.0f) return 0.0f;
    float mask = v0 + (v1 - v0) * tr;
    float idxf = phase * (float)maxi;
    idxf = fminf(fmaxf(idxf, 0.0f), (float)maxi);
    int lo = (int)floorf(idxf);
    float tt = idxf - (float)lo;
    int hi = min(lo + 1, maxi);
    float lv = __ldg(tab + lo);
    float hv = __ldg(tab + hi);
    return mask * (lv + (hv - lv) * tt);
}

__global__ void k_gen(const float* __restrict__ py48, const float* __restrict__ py144,
                      const float* __restrict__ py432) {
    const int i = blockIdx.x;
    const int j = threadIdx.x;      // 0..479
    const double base = g_base[i];
    const double c1 = g_c1[i], c2h = g_c2h[i];
    const float af = g_af[i], bf = g_bf[i];

    const double jd = (double)j;
    const double u = base + (jd + 1.0) * c1 + (jd * (jd + 1.0)) * c2h;
    const float phase = (float)(u - floor(u));
    const float f0c = af + (bf - af) * ((float)j * (1.0f / 480.0f));

    const float tr = g_trans[j];
    const unsigned vi = g_vuv[i], vn = g_vuv[i + 1];

    float acc = 0.0f;
    acc += band_lookup(py48, 48 * 1024, phase, tr, (float)(vi & 1), (float)(vn & 1));
    acc += band_lookup(py144, 144 * 1024, phase, tr, (float)((vi >> 1) & 1), (float)((vn >> 1) & 1));
    acc += band_lookup(py432, 432 * 1024, phase, tr, (float)((vi >> 2) & 1), (float)((vn >> 2) & 1));

    g_p2x[i * HOP2XC + j] = acc * f0c * (1.0f / 48000.0f);
}

// ---------------- K4: fused STFT->truncate->ISTFT via 2x 512-pt Stockham FFT ----------------
// Forward 512-pt of packed z = x[2n] + i*x[2n+1] gives the 1024-pt real FFT bins
// X[0..256]; hermitian-extend (imag dropped at DC/Nyquist), conj, second forward
// 512-pt FFT, take Re/512 -> irfft. Stockham autosort: no bit reversal.

template<int N, int S>
__device__ __forceinline__ void step4(const float2* __restrict__ src, float2* __restrict__ dst,
                                      int tid) {
    // N1*S == 128 work items, exactly one per thread
    constexpr int N1 = N / 4;
    constexpr int M = 1024 / N;     // twiddle stride
    const int p = tid / S;
    const int q = tid - p * S;
    const float2 a = src[PADI(q + S * p)];
    const float2 b = src[PADI(q + S * (p + N1))];
    const float2 c = src[PADI(q + S * (p + 2 * N1))];
    const float2 d = src[PADI(q + S * (p + 3 * N1))];
    const float2 apc = cadd(a, c);
    const float2 amc = csub(a, c);
    const float2 bpd = cadd(b, d);
    const float2 jbmd = make_float2(-(b.y - d.y), b.x - d.x);   // i*(b-d)
    const float2 w1 = __ldg(&g_tw[p * M]);
    const float2 w2 = __ldg(&g_tw[2 * p * M]);
    const float2 w3 = cmul(w1, w2);
    dst[PADI(q + S * (4 * p + 0))] = cadd(apc, bpd);
    dst[PADI(q + S * (4 * p + 1))] = cmul(w1, csub(amc, jbmd));
    dst[PADI(q + S * (4 * p + 2))] = cmul(w2, csub(apc, bpd));
    dst[PADI(q + S * (4 * p + 3))] = cmul(w3, cadd(amc, jbmd));
}

__device__ __forceinline__ void fft512(float2* __restrict__ U, float2* __restrict__ V, int tid) {
    step4<512, 1>(U, V, tid);  __syncthreads();
    step4<128, 4>(V, U, tid);  __syncthreads();
    step4<32, 16>(U, V, tid);  __syncthreads();
    step4<8, 64>(V, U, tid);   __syncthreads();
    // final radix-2: n=2, s=256 (two items per thread)
    #pragma unroll
    for (int r = 0; r < 2; r++) {
        const int q = tid + r * 128;
        const float2 a = U[PADI(q)];
        const float2 b = U[PADI(q + 256)];
        V[PADI(q)] = cadd(a, b);
        V[PADI(q + 256)] = csub(a, b);
    }
    __syncthreads();
}

__global__ void __launch_bounds__(128) k_fft() {
    __shared__ float2 U[PADSZ];
    __shared__ float2 V[PADSZ];
    const int tid = threadIdx.x;
    const int frame = blockIdx.x;

    // load 1024 samples (reflect pad), window, pack even+i*odd into 512 complex
    #pragma unroll
    for (int n0 = tid; n0 < 512; n0 += 128) {
        int ge = frame * HOP2XC - 512 + 2 * n0;
        int go = ge + 1;
        if (ge < 0) ge = -ge;
        if (ge >= L2X) ge = 2 * L2X - 2 - ge;
        if (go < 0) go = -go;
        if (go >= L2X) go = 2 * L2X - 2 - go;
        float xe = g_p2x[ge] * g_w1024[2 * n0];
        float xo = g_p2x[go] * g_w1024[2 * n0 + 1];
        U[PADI(n0)] = make_float2(xe, xo);
    }
    __syncthreads();

    fft512(U, V, tid);          // Z in V (natural order)

    // build conj(B) into U: B = hermitian extension of X[0..256] (DC/Nyquist imag dropped)
    for (int j = tid; j <= 256; j += 128) {
        const float2 Zj = V[PADI(j)];
        const float2 Zm = V[PADI((512 - j) & 511)];
        const float2 E = make_float2(0.5f * (Zj.x + Zm.x), 0.5f * (Zj.y - Zm.y));
        const float2 O = make_float2(0.5f * (Zj.y + Zm.y), -0.5f * (Zj.x - Zm.x));
        const float2 X = cadd(E, cmul(__ldg(&g_tw[j]), O));
        if (j == 0) {
            U[PADI(0)] = make_float2(X.x, 0.0f);
        } else if (j == 256) {
            U[PADI(256)] = make_float2(X.x, 0.0f);
        } else {
            U[PADI(j)] = make_float2(X.x, -X.y);       // conj(X_j)
            U[PADI(512 - j)] = make_float2(X.x, X.y);  // X_j
        }
    }
    __syncthreads();

    fft512(U, V, tid);          // FFT(conj(B)) in V

    #pragma unroll
    for (int m = tid; m < 512; m += 128) {
        g_ybuf[frame * 512 + m] = V[PADI(m)].x * (1.0f / 512.0f) * g_w512[m];
    }
}

// ---------------- K5: deterministic OLA gather + env normalize ----------------
__global__ void k_ola(float* __restrict__ out) {
    int n = blockIdx.x * blockDim.x + threadIdx.x;
    if (n >= OUTLEN) return;
    const int s = n + 256;
    int tlo = (s >= 512) ? (s - 511 + 239) / 240 : 0;
    int thi = s / 240;
    if (thi > NFRAMES) thi = NFRAMES;
    float sig = 0.0f, env = 0.0f;
    for (int t = tlo; t <= thi; t++) {
        const int m = s - 240 * t;
        const float w = g_w512[m];
        sig += g_ybuf[t * 512 + m];
        env += w * w;
    }
    out[n] = (env > 1e-11f) ? (sig / env) : 0.0f;
}

// ---------------- launcher ----------------
extern "C" void kernel_launch(void* const* d_in, const int* in_sizes, int n_in,
                              void* d_out, int out_size) {
    const float* f0    = (const float*)d_in[0];
    const float* py48  = (const float*)d_in[1];
    const float* py144 = (const float*)d_in[2];
    const float* py432 = (const float*)d_in[3];
    float* out = (float*)d_out;
    (void)in_sizes; (void)n_in; (void)out_size;

    k_setup<<<1, 1024>>>();
    k_frames<<<(NFRAMES + 255) / 256, 256>>>(f0);
    k_scan<<<1, 256>>>();
    k_gen<<<NFRAMES, HOP2XC>>>(py48, py144, py432);
    k_fft<<<NSTFT, 128>>>();
    k_ola<<<(OUTLEN + 255) / 256, 256>>>(out);
}

// round 3
// speedup vs baseline: 2.6571x; 1.1183x over previous
#include <cuda_runtime.h>
#include <math.h>

#define NFRAMES   16384
#define HOPC      240
#define HOP2XC    480
#define L2X       (NFRAMES*HOP2XC)      /* 7,864,320 */
#define NSTFT     (NFRAMES+1)           /* 16385 */
#define OUTLEN    (NFRAMES*HOPC)        /* 3,932,160 */
#define PI_D      3.14159265358979323846

// ---------------- static device scratch ----------------
__device__ float  g_p2x[L2X];
__device__ float  g_ybuf[NSTFT * 512];
__device__ double g_S[NFRAMES];
__device__ double g_base[NFRAMES];
__device__ double g_c1[NFRAMES];
__device__ double g_c2h[NFRAMES];
__device__ float  g_af[NFRAMES];
__device__ float  g_bf[NFRAMES];
__device__ unsigned char g_vuv[NFRAMES + 1];
__device__ float  g_w1024[1024];
__device__ float  g_w512[512];
__device__ float2 g_tw[1024];                 // exp(-2*pi*i*k/1024)
__device__ float  g_trans[HOP2XC];

// ---------------- helpers ----------------
__device__ __forceinline__ float2 cmul(float2 a, float2 b) {
    return make_float2(a.x * b.x - a.y * b.y, a.x * b.y + a.y * b.x);
}
__device__ __forceinline__ float2 cadd(float2 a, float2 b) { return make_float2(a.x + b.x, a.y + b.y); }
__device__ __forceinline__ float2 csub(float2 a, float2 b) { return make_float2(a.x - b.x, a.y - b.y); }
__device__ __forceinline__ float2 jmul(float2 a) { return make_float2(-a.y, a.x); }   // i*a

#define PADI(i) ((i) + ((i) >> 3))   /* pad every 8 float2 */
#define PADSZ   (512 + 64)

// ---------------- K0: tables ----------------
__global__ void k_setup() {
    int t = threadIdx.x;  // 1024 threads
    g_w1024[t] = (float)(0.5 - 0.5 * cos(2.0 * PI_D * (double)t / 1024.0));
    double ang = -2.0 * PI_D * (double)t / 1024.0;
    g_tw[t] = make_float2((float)cos(ang), (float)sin(ang));
    if (t < 512) g_w512[t] = (float)(0.5 - 0.5 * cos(2.0 * PI_D * (double)t / 512.0));
    if (t < HOP2XC) {
        double s = sin(((double)t / (double)HOP2XC) * (PI_D * 0.5));
        g_trans[t] = (float)(s * s);
    }
}

// ---------------- K1: per-frame values ----------------
__global__ void k_frames(const float* __restrict__ f0) {
    int i = blockIdx.x * blockDim.x + threadIdx.x;
    if (i >= NFRAMES) return;
    double fi = (double)f0[i];
    double fn = (i + 1 < NFRAMES) ? (double)f0[i + 1] : 0.0;
    double a = (fi != 0.0) ? fi : fn;
    double b = (fn != 0.0) ? fn : fi;
    g_af[i] = (float)a;
    g_bf[i] = (float)b;
    g_c1[i] = a / 96000.0;
    g_c2h[i] = (b - a) / (2.0 * 480.0 * 96000.0);
    g_S[i] = (480.0 * a + (b - a) * (114960.0 / 480.0)) / 96000.0;
    unsigned char m = 0;
    if (fi >= 500.0 && fi < 1500.0) m |= 1;
    if (fi >= (24000.0 / 144.0) && fi < 500.0) m |= 2;
    if (fi >= (24000.0 / 432.0) && fi < (24000.0 / 144.0)) m |= 4;
    g_vuv[i] = m;
    if (i == NFRAMES - 1) g_vuv[NFRAMES] = 0;
}

// ---------------- K2: frame-level scan (mod 1), one block ----------------
__global__ void k_scan() {
    __shared__ double sh[256];
    const int t = threadIdx.x;
    const int b0 = t * 64;
    double s = 0.0;
    for (int j = 0; j < 64; j++) s += g_S[b0 + j];
    sh[t] = s;
    __syncthreads();
    for (int off = 1; off < 256; off <<= 1) {
        double v = (t >= off) ? sh[t - off] : 0.0;
        __syncthreads();
        sh[t] += v;
        __syncthreads();
    }
    double base = (t > 0) ? sh[t - 1] : 0.0;
    for (int j = 0; j < 64; j++) {
        g_base[b0 + j] = fmod(base, 1.0);
        base += g_S[b0 + j];
    }
}

// ---------------- K3: excitation at 2x rate, 4 samples/thread ----------------
__device__ __forceinline__ float band_lookup(const float* __restrict__ tab, int maxi,
                                             float phase, float tr, float v0, float v1) {
    if (v0 == 0.0f && v1 == 0.0f) return 0.0f;
    float mask = v0 + (v1 - v0) * tr;
    float idxf = phase * (float)maxi;
    idxf = fminf(fmaxf(idxf, 0.0f), (float)maxi);
    int lo = (int)floorf(idxf);
    float tt = idxf - (float)lo;
    int hi = min(lo + 1, maxi);
    float lv = __ldg(tab + lo);
    float hv = __ldg(tab + hi);
    return mask * (lv + (hv - lv) * tt);
}

__global__ void __launch_bounds__(256) k_gen(const float* __restrict__ py48,
                                             const float* __restrict__ py144,
                                             const float* __restrict__ py432) {
    const int t = blockIdx.x * blockDim.x + threadIdx.x;   // L2X/4 threads
    const int s0 = t * 4;
    const int i = s0 / 480;
    const int j0 = s0 - i * 480;                            // 0..476, all 4 in same frame

    const double base = g_base[i];
    const double c1 = g_c1[i], c2h = g_c2h[i];
    const float af = g_af[i], bf = g_bf[i];
    const unsigned vi = g_vuv[i], vn = g_vuv[i + 1];
    const float v48a = (float)(vi & 1),        v48b = (float)(vn & 1);
    const float v144a = (float)((vi >> 1) & 1), v144b = (float)((vn >> 1) & 1);
    const float v432a = (float)((vi >> 2) & 1), v432b = (float)((vn >> 2) & 1);

    float ph[4], trv[4], f0cv[4];
    #pragma unroll
    for (int r = 0; r < 4; r++) {
        const double jd = (double)(j0 + r);
        const double u = base + (jd + 1.0) * c1 + (jd * (jd + 1.0)) * c2h;
        ph[r] = (float)(u - floor(u));
        trv[r] = g_trans[j0 + r];
        f0cv[r] = af + (bf - af) * ((float)(j0 + r) * (1.0f / 480.0f));
    }

    float4 out;
    float* op = (float*)&out;
    #pragma unroll
    for (int r = 0; r < 4; r++) {
        float acc = 0.0f;
        acc += band_lookup(py48, 48 * 1024, ph[r], trv[r], v48a, v48b);
        acc += band_lookup(py144, 144 * 1024, ph[r], trv[r], v144a, v144b);
        acc += band_lookup(py432, 432 * 1024, ph[r], trv[r], v432a, v432b);
        op[r] = acc * f0cv[r] * (1.0f / 48000.0f);
    }
    *(float4*)(g_p2x + s0) = out;
}

// ---------------- K4: radix-8 Stockham, 64 threads, 3 stages per 512-pt FFT ----------------
template<int N, int S>
__device__ __forceinline__ void step8(const float2* __restrict__ src, float2* __restrict__ dst,
                                      int t) {
    constexpr int N1 = N / 8;
    constexpr int M = 1024 / N;      // g_tw is a 1024-root table
    const int p = t / S;
    const int q = t - p * S;

    float2 x[8];
    #pragma unroll
    for (int r = 0; r < 8; r++) x[r] = src[PADI(q + S * (p + r * N1))];

    // DFT8 via two DFT4s (even/odd) + combine
    float2 ea = cadd(x[0], x[4]), eb = csub(x[0], x[4]);
    float2 ec = cadd(x[2], x[6]), ed = csub(x[2], x[6]);
    float2 E0 = cadd(ea, ec), E2 = csub(ea, ec);
    float2 E1 = csub(eb, jmul(ed)), E3 = cadd(eb, jmul(ed));

    float2 oa = cadd(x[1], x[5]), ob = csub(x[1], x[5]);
    float2 oc = cadd(x[3], x[7]), od = csub(x[3], x[7]);
    float2 O0 = cadd(oa, oc), O2 = csub(oa, oc);
    float2 O1 = csub(ob, jmul(od)), O3 = cadd(ob, jmul(od));

    // t_r = e^{-2 pi i r/8}
    const float C = 0.70710678118654752440f;
    float2 T1 = make_float2(C * (O1.x + O1.y), C * (O1.y - O1.x));   // (c-ic)*O1
    float2 T2 = make_float2(O2.y, -O2.x);                             // -i*O2
    float2 T3 = make_float2(C * (O3.y - O3.x), -C * (O3.x + O3.y));  // (-c-ic)*O3

    float2 Y[8];
    Y[0] = cadd(E0, O0); Y[4] = csub(E0, O0);
    Y[1] = cadd(E1, T1); Y[5] = csub(E1, T1);
    Y[2] = cadd(E2, T2); Y[6] = csub(E2, T2);
    Y[3] = cadd(E3, T3); Y[7] = csub(E3, T3);

    if (N == 8) {
        // p == 0 always: twiddle-free
        #pragma unroll
        for (int r = 0; r < 8; r++) dst[PADI(q + S * (8 * p + r))] = Y[r];
    } else {
        const float2 w1 = __ldg(&g_tw[p * M]);
        const float2 w2 = cmul(w1, w1);
        const float2 w3 = cmul(w2, w1);
        const float2 w4 = cmul(w2, w2);
        const float2 w5 = cmul(w4, w1);
        const float2 w6 = cmul(w4, w2);
        const float2 w7 = cmul(w4, w3);
        dst[PADI(q + S * (8 * p + 0))] = Y[0];
        dst[PADI(q + S * (8 * p + 1))] = cmul(w1, Y[1]);
        dst[PADI(q + S * (8 * p + 2))] = cmul(w2, Y[2]);
        dst[PADI(q + S * (8 * p + 3))] = cmul(w3, Y[3]);
        dst[PADI(q + S * (8 * p + 4))] = cmul(w4, Y[4]);
        dst[PADI(q + S * (8 * p + 5))] = cmul(w5, Y[5]);
        dst[PADI(q + S * (8 * p + 6))] = cmul(w6, Y[6]);
        dst[PADI(q + S * (8 * p + 7))] = cmul(w7, Y[7]);
    }
}

__device__ __forceinline__ void fft512(float2* __restrict__ U, float2* __restrict__ V, int t) {
    step8<512, 1>(U, V, t);  __syncthreads();
    step8<64, 8>(V, U, t);   __syncthreads();
    step8<8, 64>(U, V, t);   __syncthreads();
    // result in V, natural order
}

__global__ void __launch_bounds__(64) k_fft() {
    __shared__ float2 U[PADSZ];
    __shared__ float2 V[PADSZ];
    const int t = threadIdx.x;
    const int frame = blockIdx.x;

    // load 1024 samples (reflect pad), window, pack even + i*odd -> 512 complex
    #pragma unroll
    for (int n0 = t; n0 < 512; n0 += 64) {
        int ge = frame * HOP2XC - 512 + 2 * n0;
        int go = ge + 1;
        if (ge < 0) ge = -ge;
        if (ge >= L2X) ge = 2 * L2X - 2 - ge;
        if (go < 0) go = -go;
        if (go >= L2X) go = 2 * L2X - 2 - go;
        float xe = g_p2x[ge] * g_w1024[2 * n0];
        float xo = g_p2x[go] * g_w1024[2 * n0 + 1];
        U[PADI(n0)] = make_float2(xe, xo);
    }
    __syncthreads();

    fft512(U, V, t);            // Z in V

    // conj of hermitian-extended X[0..256] (imag dropped at DC/Nyquist), into U
    for (int j = t; j <= 256; j += 64) {
        const float2 Zj = V[PADI(j)];
        const float2 Zm = V[PADI((512 - j) & 511)];
        const float2 E = make_float2(0.5f * (Zj.x + Zm.x), 0.5f * (Zj.y - Zm.y));
        const float2 O = make_float2(0.5f * (Zj.y + Zm.y), -0.5f * (Zj.x - Zm.x));
        const float2 X = cadd(E, cmul(__ldg(&g_tw[j]), O));
        if (j == 0) {
            U[PADI(0)] = make_float2(X.x, 0.0f);
        } else if (j == 256) {
            U[PADI(256)] = make_float2(X.x, 0.0f);
        } else {
            U[PADI(j)] = make_float2(X.x, -X.y);
            U[PADI(512 - j)] = make_float2(X.x, X.y);
        }
    }
    __syncthreads();

    fft512(U, V, t);            // FFT(conj(B)) in V

    #pragma unroll
    for (int m = t; m < 512; m += 64) {
        g_ybuf[frame * 512 + m] = V[PADI(m)].x * (1.0f / 512.0f) * g_w512[m];
    }
}

// ---------------- K5: deterministic OLA gather + env normalize ----------------
__global__ void k_ola(float* __restrict__ out) {
    int n = blockIdx.x * blockDim.x + threadIdx.x;
    if (n >= OUTLEN) return;
    const int s = n + 256;
    int tlo = (s >= 512) ? (s - 511 + 239) / 240 : 0;
    int thi = s / 240;
    if (thi > NFRAMES) thi = NFRAMES;
    float sig = 0.0f, env = 0.0f;
    for (int t = tlo; t <= thi; t++) {
        const int m = s - 240 * t;
        const float w = g_w512[m];
        sig += g_ybuf[t * 512 + m];
        env += w * w;
    }
    out[n] = (env > 1e-11f) ? (sig / env) : 0.0f;
}

// ---------------- launcher ----------------
extern "C" void kernel_launch(void* const* d_in, const int* in_sizes, int n_in,
                              void* d_out, int out_size) {
    const float* f0    = (const float*)d_in[0];
    const float* py48  = (const float*)d_in[1];
    const float* py144 = (const float*)d_in[2];
    const float* py432 = (const float*)d_in[3];
    float* out = (float*)d_out;
    (void)in_sizes; (void)n_in; (void)out_size;

    k_setup<<<1, 1024>>>();
    k_frames<<<(NFRAMES + 255) / 256, 256>>>(f0);
    k_scan<<<1, 256>>>();
    k_gen<<<L2X / 4 / 256, 256>>>(py48, py144, py432);
    k_fft<<<NSTFT, 64>>>();
    k_ola<<<(OUTLEN + 255) / 256, 256>>>(out);
}

// round 4
// speedup vs baseline: 2.7146x; 1.0216x over previous
#include <cuda_runtime.h>
#include <math.h>

#define NFRAMES   16384
#define HOPC      240
#define HOP2XC    480
#define L2X       (NFRAMES*HOP2XC)      /* 7,864,320 */
#define NSTFT     (NFRAMES+1)           /* 16385 */
#define OUTLEN    (NFRAMES*HOPC)        /* 3,932,160 */
#define PI_D      3.14159265358979323846

#define LEN48   (48*1024+1)
#define LEN144  (144*1024+1)
#define LEN432  (432*1024+1)

// ---------------- static device scratch ----------------
__device__ float  g_p2x[L2X];
__device__ float  g_ybuf[NSTFT * 512];
__device__ double g_S[NFRAMES];
__device__ double g_base[NFRAMES];
__device__ double g_c1[NFRAMES];
__device__ double g_c2h[NFRAMES];
__device__ float  g_af[NFRAMES];
__device__ float  g_bf[NFRAMES];
__device__ unsigned char g_vuv[NFRAMES + 1];
__device__ float  g_w1024[1024];
__device__ float  g_w512[512];
__device__ float2 g_tw[1024];                 // exp(-2*pi*i*k/1024)
__device__ float  g_trans[HOP2XC];
__device__ float2 g_pr48[LEN48];              // {y[i], y[i+1]} pairs
__device__ float2 g_pr144[LEN144];
__device__ float2 g_pr432[LEN432];

// ---------------- helpers ----------------
__device__ __forceinline__ float2 cmul(float2 a, float2 b) {
    return make_float2(a.x * b.x - a.y * b.y, a.x * b.y + a.y * b.x);
}
__device__ __forceinline__ float2 cadd(float2 a, float2 b) { return make_float2(a.x + b.x, a.y + b.y); }
__device__ __forceinline__ float2 csub(float2 a, float2 b) { return make_float2(a.x - b.x, a.y - b.y); }
__device__ __forceinline__ float2 jmul(float2 a) { return make_float2(-a.y, a.x); }   // i*a

#define PADI(i) ((i) + ((i) >> 3))   /* pad every 8 float2 */
#define PADSZ   (512 + 64)

// ---------------- K0: tables ----------------
__global__ void k_setup() {
    int t = threadIdx.x;  // 1024 threads
    g_w1024[t] = (float)(0.5 - 0.5 * cos(2.0 * PI_D * (double)t / 1024.0));
    double ang = -2.0 * PI_D * (double)t / 1024.0;
    g_tw[t] = make_float2((float)cos(ang), (float)sin(ang));
    if (t < 512) g_w512[t] = (float)(0.5 - 0.5 * cos(2.0 * PI_D * (double)t / 512.0));
    if (t < HOP2XC) {
        double s = sin(((double)t / (double)HOP2XC) * (PI_D * 0.5));
        g_trans[t] = (float)(s * s);
    }
}

// ---------------- K0b: build {y[i], y[i+1]} pair tables ----------------
__global__ void k_pairs(const float* __restrict__ py48, const float* __restrict__ py144,
                        const float* __restrict__ py432) {
    int i = blockIdx.x * blockDim.x + threadIdx.x;
    if (i < LEN48)  g_pr48[i]  = make_float2(py48[i],  py48[min(i + 1, LEN48 - 1)]);
    if (i < LEN144) g_pr144[i] = make_float2(py144[i], py144[min(i + 1, LEN144 - 1)]);
    if (i < LEN432) g_pr432[i] = make_float2(py432[i], py432[min(i + 1, LEN432 - 1)]);
}

// ---------------- K1: per-frame values ----------------
__global__ void k_frames(const float* __restrict__ f0) {
    int i = blockIdx.x * blockDim.x + threadIdx.x;
    if (i >= NFRAMES) return;
    double fi = (double)f0[i];
    double fn = (i + 1 < NFRAMES) ? (double)f0[i + 1] : 0.0;
    double a = (fi != 0.0) ? fi : fn;
    double b = (fn != 0.0) ? fn : fi;
    g_af[i] = (float)a;
    g_bf[i] = (float)b;
    g_c1[i] = a / 96000.0;
    g_c2h[i] = (b - a) / (2.0 * 480.0 * 96000.0);
    g_S[i] = (480.0 * a + (b - a) * (114960.0 / 480.0)) / 96000.0;
    unsigned char m = 0;
    if (fi >= 500.0 && fi < 1500.0) m |= 1;
    if (fi >= (24000.0 / 144.0) && fi < 500.0) m |= 2;
    if (fi >= (24000.0 / 432.0) && fi < (24000.0 / 144.0)) m |= 4;
    g_vuv[i] = m;
    if (i == NFRAMES - 1) g_vuv[NFRAMES] = 0;
}

// ---------------- K2: frame-level scan (mod 1), one block ----------------
__global__ void k_scan() {
    __shared__ double sh[256];
    const int t = threadIdx.x;
    const int b0 = t * 64;
    double s = 0.0;
    for (int j = 0; j < 64; j++) s += g_S[b0 + j];
    sh[t] = s;
    __syncthreads();
    for (int off = 1; off < 256; off <<= 1) {
        double v = (t >= off) ? sh[t - off] : 0.0;
        __syncthreads();
        sh[t] += v;
        __syncthreads();
    }
    double base = (t > 0) ? sh[t - 1] : 0.0;
    for (int j = 0; j < 64; j++) {
        g_base[b0 + j] = fmod(base, 1.0);
        base += g_S[b0 + j];
    }
}

// ---------------- K3: excitation at 2x rate, 4 samples/thread, paired-table lookups ----
__device__ __forceinline__ float band_lookup(const float2* __restrict__ pair, int maxi,
                                             float phase, float tr, float v0, float v1) {
    if (v0 == 0.0f && v1 == 0.0f) return 0.0f;
    float mask = v0 + (v1 - v0) * tr;
    float idxf = phase * (float)maxi;
    idxf = fminf(fmaxf(idxf, 0.0f), (float)maxi);
    int lo = (int)floorf(idxf);
    float tt = idxf - (float)lo;
    float2 p = __ldg(pair + lo);
    return mask * (p.x + (p.y - p.x) * tt);
}

__global__ void __launch_bounds__(256) k_gen() {
    const int t = blockIdx.x * blockDim.x + threadIdx.x;   // L2X/4 threads
    const int s0 = t * 4;
    const int i = s0 / 480;
    const int j0 = s0 - i * 480;                            // all 4 in same frame

    const double base = g_base[i];
    const double c1 = g_c1[i], c2h = g_c2h[i];
    const float af = g_af[i], bf = g_bf[i];
    const unsigned vi = g_vuv[i], vn = g_vuv[i + 1];
    const float v48a = (float)(vi & 1),         v48b = (float)(vn & 1);
    const float v144a = (float)((vi >> 1) & 1), v144b = (float)((vn >> 1) & 1);
    const float v432a = (float)((vi >> 2) & 1), v432b = (float)((vn >> 2) & 1);

    float ph[4], trv[4], f0cv[4];
    #pragma unroll
    for (int r = 0; r < 4; r++) {
        const double jd = (double)(j0 + r);
        const double u = base + (jd + 1.0) * c1 + (jd * (jd + 1.0)) * c2h;
        ph[r] = (float)(u - floor(u));
        trv[r] = g_trans[j0 + r];
        f0cv[r] = af + (bf - af) * ((float)(j0 + r) * (1.0f / 480.0f));
    }

    float4 out;
    float* op = (float*)&out;
    #pragma unroll
    for (int r = 0; r < 4; r++) {
        float acc = 0.0f;
        acc += band_lookup(g_pr48, 48 * 1024, ph[r], trv[r], v48a, v48b);
        acc += band_lookup(g_pr144, 144 * 1024, ph[r], trv[r], v144a, v144b);
        acc += band_lookup(g_pr432, 432 * 1024, ph[r], trv[r], v432a, v432b);
        op[r] = acc * f0cv[r] * (1.0f / 48000.0f);
    }
    *(float4*)(g_p2x + s0) = out;
}

// ---------------- K4: radix-8 Stockham, 2 frames per 128-thread block ----------------
template<int N, int S>
__device__ __forceinline__ void step8(const float2* __restrict__ src, float2* __restrict__ dst,
                                      int t) {
    constexpr int N1 = N / 8;
    constexpr int M = 1024 / N;
    const int p = t / S;
    const int q = t - p * S;

    float2 x[8];
    #pragma unroll
    for (int r = 0; r < 8; r++) x[r] = src[PADI(q + S * (p + r * N1))];

    float2 ea = cadd(x[0], x[4]), eb = csub(x[0], x[4]);
    float2 ec = cadd(x[2], x[6]), ed = csub(x[2], x[6]);
    float2 E0 = cadd(ea, ec), E2 = csub(ea, ec);
    float2 E1 = csub(eb, jmul(ed)), E3 = cadd(eb, jmul(ed));

    float2 oa = cadd(x[1], x[5]), ob = csub(x[1], x[5]);
    float2 oc = cadd(x[3], x[7]), od = csub(x[3], x[7]);
    float2 O0 = cadd(oa, oc), O2 = csub(oa, oc);
    float2 O1 = csub(ob, jmul(od)), O3 = cadd(ob, jmul(od));

    const float C = 0.70710678118654752440f;
    float2 T1 = make_float2(C * (O1.x + O1.y), C * (O1.y - O1.x));
    float2 T2 = make_float2(O2.y, -O2.x);
    float2 T3 = make_float2(C * (O3.y - O3.x), -C * (O3.x + O3.y));

    float2 Y[8];
    Y[0] = cadd(E0, O0); Y[4] = csub(E0, O0);
    Y[1] = cadd(E1, T1); Y[5] = csub(E1, T1);
    Y[2] = cadd(E2, T2); Y[6] = csub(E2, T2);
    Y[3] = cadd(E3, T3); Y[7] = csub(E3, T3);

    if (N == 8) {
        #pragma unroll
        for (int r = 0; r < 8; r++) dst[PADI(q + S * (8 * p + r))] = Y[r];
    } else {
        const float2 w1 = __ldg(&g_tw[p * M]);
        const float2 w2 = cmul(w1, w1);
        const float2 w3 = cmul(w2, w1);
        const float2 w4 = cmul(w2, w2);
        const float2 w5 = cmul(w4, w1);
        const float2 w6 = cmul(w4, w2);
        const float2 w7 = cmul(w4, w3);
        dst[PADI(q + S * (8 * p + 0))] = Y[0];
        dst[PADI(q + S * (8 * p + 1))] = cmul(w1, Y[1]);
        dst[PADI(q + S * (8 * p + 2))] = cmul(w2, Y[2]);
        dst[PADI(q + S * (8 * p + 3))] = cmul(w3, Y[3]);
        dst[PADI(q + S * (8 * p + 4))] = cmul(w4, Y[4]);
        dst[PADI(q + S * (8 * p + 5))] = cmul(w5, Y[5]);
        dst[PADI(q + S * (8 * p + 6))] = cmul(w6, Y[6]);
        dst[PADI(q + S * (8 * p + 7))] = cmul(w7, Y[7]);
    }
}

__device__ __forceinline__ void fft512(float2* __restrict__ U, float2* __restrict__ V, int t) {
    step8<512, 1>(U, V, t);  __syncthreads();
    step8<64, 8>(V, U, t);   __syncthreads();
    step8<8, 64>(U, V, t);   __syncthreads();
}

__global__ void __launch_bounds__(128) k_fft() {
    __shared__ float2 Ub[2][PADSZ];
    __shared__ float2 Vb[2][PADSZ];
    const int tid = threadIdx.x;
    const int sub = tid >> 6;            // 0 or 1: which frame lane
    const int t = tid & 63;
    const int frame = blockIdx.x * 2 + sub;
    const bool valid = (frame < NSTFT);

    float2* U = Ub[sub];
    float2* V = Vb[sub];

    // load 1024 samples (reflect pad), window, pack even + i*odd -> 512 complex
    #pragma unroll
    for (int n0 = t; n0 < 512; n0 += 64) {
        float xe = 0.0f, xo = 0.0f;
        if (valid) {
            int ge = frame * HOP2XC - 512 + 2 * n0;
            if (ge >= 0 && ge + 1 < L2X) {
                float2 v = *(const float2*)(g_p2x + ge);   // aligned: ge even
                xe = v.x; xo = v.y;
            } else {
                int go = ge + 1;
                if (ge < 0) ge = -ge;
                if (ge >= L2X) ge = 2 * L2X - 2 - ge;
                if (go < 0) go = -go;
                if (go >= L2X) go = 2 * L2X - 2 - go;
                xe = g_p2x[ge];
                xo = g_p2x[go];
            }
            xe *= g_w1024[2 * n0];
            xo *= g_w1024[2 * n0 + 1];
        }
        U[PADI(n0)] = make_float2(xe, xo);
    }
    __syncthreads();

    fft512(U, V, t);            // Z in V

    // conj of hermitian-extended X[0..256] (imag dropped at DC/Nyquist), into U
    for (int j = t; j <= 256; j += 64) {
        const float2 Zj = V[PADI(j)];
        const float2 Zm = V[PADI((512 - j) & 511)];
        const float2 E = make_float2(0.5f * (Zj.x + Zm.x), 0.5f * (Zj.y - Zm.y));
        const float2 O = make_float2(0.5f * (Zj.y + Zm.y), -0.5f * (Zj.x - Zm.x));
        const float2 X = cadd(E, cmul(__ldg(&g_tw[j]), O));
        if (j == 0) {
            U[PADI(0)] = make_float2(X.x, 0.0f);
        } else if (j == 256) {
            U[PADI(256)] = make_float2(X.x, 0.0f);
        } else {
            U[PADI(j)] = make_float2(X.x, -X.y);
            U[PADI(512 - j)] = make_float2(X.x, X.y);
        }
    }
    __syncthreads();

    fft512(U, V, t);            // FFT(conj(B)) in V

    if (valid) {
        #pragma unroll
        for (int m = t; m < 512; m += 64) {
            g_ybuf[frame * 512 + m] = V[PADI(m)].x * (1.0f / 512.0f) * g_w512[m];
        }
    }
}

// ---------------- K5: deterministic OLA gather + env normalize ----------------
__global__ void k_ola(float* __restrict__ out) {
    int n = blockIdx.x * blockDim.x + threadIdx.x;
    if (n >= OUTLEN) return;
    const int s = n + 256;
    int tlo = (s >= 512) ? (s - 511 + 239) / 240 : 0;
    int thi = s / 240;
    if (thi > NFRAMES) thi = NFRAMES;
    float sig = 0.0f, env = 0.0f;
    for (int t = tlo; t <= thi; t++) {
        const int m = s - 240 * t;
        const float w = g_w512[m];
        sig += g_ybuf[t * 512 + m];
        env += w * w;
    }
    out[n] = (env > 1e-11f) ? (sig / env) : 0.0f;
}

// ---------------- launcher ----------------
extern "C" void kernel_launch(void* const* d_in, const int* in_sizes, int n_in,
                              void* d_out, int out_size) {
    const float* f0    = (const float*)d_in[0];
    const float* py48  = (const float*)d_in[1];
    const float* py144 = (const float*)d_in[2];
    const float* py432 = (const float*)d_in[3];
    float* out = (float*)d_out;
    (void)in_sizes; (void)n_in; (void)out_size;

    k_setup<<<1, 1024>>>();
    k_pairs<<<(LEN432 + 255) / 256, 256>>>(py48, py144, py432);
    k_frames<<<(NFRAMES + 255) / 256, 256>>>(f0);
    k_scan<<<1, 256>>>();
    k_gen<<<L2X / 4 / 256, 256>>>();
    k_fft<<<(NSTFT + 1) / 2, 128>>>();
    k_ola<<<(OUTLEN + 255) / 256, 256>>>(out);
}

// round 5
// speedup vs baseline: 3.0949x; 1.1401x over previous
#include <cuda_runtime.h>
#include <math.h>

#define NFRAMES   16384
#define HOPC      240
#define HOP2XC    480
#define L2X       (NFRAMES*HOP2XC)      /* 7,864,320 */
#define NSTFT     (NFRAMES+1)           /* 16385 */
#define OUTLEN    (NFRAMES*HOPC)        /* 3,932,160 */
#define PI_D      3.14159265358979323846

#define LEN48   (48*1024+1)
#define LEN144  (144*1024+1)
#define LEN432  (432*1024+1)

// ---------------- static device scratch ----------------
__device__ float  g_p2x[L2X];
__device__ float  g_ybuf[NSTFT * 512];
__device__ double g_S[NFRAMES];
__device__ double g_base[NFRAMES];
__device__ double g_c1[NFRAMES];
__device__ double g_c2h[NFRAMES];
__device__ float  g_af[NFRAMES];
__device__ float  g_bf[NFRAMES];
__device__ unsigned char g_vuv[NFRAMES + 1];
__device__ float  g_w1024[1024];
__device__ float  g_w512[512];
__device__ float2 g_tw[1024];                 // exp(-2*pi*i*k/1024)
__device__ float  g_trans[HOP2XC];
__device__ float2 g_pr48[LEN48];              // {y[i], y[i+1]} pairs
__device__ float2 g_pr144[LEN144];
__device__ float2 g_pr432[LEN432];

// ---------------- helpers ----------------
__device__ __forceinline__ float2 cmul(float2 a, float2 b) {
    return make_float2(a.x * b.x - a.y * b.y, a.x * b.y + a.y * b.x);
}
__device__ __forceinline__ float2 cadd(float2 a, float2 b) { return make_float2(a.x + b.x, a.y + b.y); }
__device__ __forceinline__ float2 csub(float2 a, float2 b) { return make_float2(a.x - b.x, a.y - b.y); }
__device__ __forceinline__ float2 jmul(float2 a) { return make_float2(-a.y, a.x); }   // i*a

#define PADI(i) ((i) + ((i) >> 3))   /* pad every 8 float2 */
#define PADSZ   (512 + 64)

// ---------------- K0: tables ----------------
__global__ void k_setup() {
    int t = threadIdx.x;  // 1024 threads
    g_w1024[t] = (float)(0.5 - 0.5 * cos(2.0 * PI_D * (double)t / 1024.0));
    double ang = -2.0 * PI_D * (double)t / 1024.0;
    g_tw[t] = make_float2((float)cos(ang), (float)sin(ang));
    if (t < 512) g_w512[t] = (float)(0.5 - 0.5 * cos(2.0 * PI_D * (double)t / 512.0));
    if (t < HOP2XC) {
        double s = sin(((double)t / (double)HOP2XC) * (PI_D * 0.5));
        g_trans[t] = (float)(s * s);
    }
}

// ---------------- K0b: build {y[i], y[i+1]} pair tables ----------------
__global__ void k_pairs(const float* __restrict__ py48, const float* __restrict__ py144,
                        const float* __restrict__ py432) {
    int i = blockIdx.x * blockDim.x + threadIdx.x;
    if (i < LEN48)  g_pr48[i]  = make_float2(py48[i],  py48[min(i + 1, LEN48 - 1)]);
    if (i < LEN144) g_pr144[i] = make_float2(py144[i], py144[min(i + 1, LEN144 - 1)]);
    if (i < LEN432) g_pr432[i] = make_float2(py432[i], py432[min(i + 1, LEN432 - 1)]);
}

// ---------------- K1: per-frame values ----------------
__global__ void k_frames(const float* __restrict__ f0) {
    int i = blockIdx.x * blockDim.x + threadIdx.x;
    if (i >= NFRAMES) return;
    double fi = (double)f0[i];
    double fn = (i + 1 < NFRAMES) ? (double)f0[i + 1] : 0.0;
    double a = (fi != 0.0) ? fi : fn;
    double b = (fn != 0.0) ? fn : fi;
    g_af[i] = (float)a;
    g_bf[i] = (float)b;
    g_c1[i] = a / 96000.0;
    g_c2h[i] = (b - a) / (2.0 * 480.0 * 96000.0);
    g_S[i] = (480.0 * a + (b - a) * (114960.0 / 480.0)) / 96000.0;
    unsigned char m = 0;
    if (fi >= 500.0 && fi < 1500.0) m |= 1;
    if (fi >= (24000.0 / 144.0) && fi < 500.0) m |= 2;
    if (fi >= (24000.0 / 432.0) && fi < (24000.0 / 144.0)) m |= 4;
    g_vuv[i] = m;
    if (i == NFRAMES - 1) g_vuv[NFRAMES] = 0;
}

// ---------------- K2: frame-level scan, 1024 threads x 16 elems, shfl-based --------
__global__ void __launch_bounds__(1024) k_scan() {
    __shared__ double warpsum[32];
    const int t = threadIdx.x;
    const int lane = t & 31;
    const int wid = t >> 5;
    const int b0 = t * 16;

    double loc[16];
    double s = 0.0;
    #pragma unroll
    for (int j = 0; j < 16; j++) { loc[j] = g_S[b0 + j]; s += loc[j]; }

    // warp-inclusive scan of per-thread sums
    double v = s;
    #pragma unroll
    for (int off = 1; off < 32; off <<= 1) {
        double n = __shfl_up_sync(0xffffffffu, v, off);
        if (lane >= off) v += n;
    }
    if (lane == 31) warpsum[wid] = v;
    __syncthreads();
    if (wid == 0) {
        double w = warpsum[lane];
        #pragma unroll
        for (int off = 1; off < 32; off <<= 1) {
            double n = __shfl_up_sync(0xffffffffu, w, off);
            if (lane >= off) w += n;
        }
        warpsum[lane] = w;
    }
    __syncthreads();

    double base = (v - s) + ((wid > 0) ? warpsum[wid - 1] : 0.0);  // exclusive prefix
    #pragma unroll
    for (int j = 0; j < 16; j++) {
        g_base[b0 + j] = base - floor(base);   // == fmod(base,1) for base >= 0
        base += loc[j];
    }
}

// ---------------- K3: excitation at 2x rate, 4 samples/thread, paired-table lookups ----
__device__ __forceinline__ float band_lookup(const float2* __restrict__ pair, int maxi,
                                             float phase, float tr, float v0, float v1) {
    if (v0 == 0.0f && v1 == 0.0f) return 0.0f;
    float mask = v0 + (v1 - v0) * tr;
    float idxf = phase * (float)maxi;
    idxf = fminf(fmaxf(idxf, 0.0f), (float)maxi);
    int lo = (int)floorf(idxf);
    float tt = idxf - (float)lo;
    float2 p = __ldg(pair + lo);
    return mask * (p.x + (p.y - p.x) * tt);
}

__global__ void __launch_bounds__(256) k_gen() {
    const int t = blockIdx.x * blockDim.x + threadIdx.x;   // L2X/4 threads
    const int s0 = t * 4;
    const int i = s0 / 480;
    const int j0 = s0 - i * 480;                            // all 4 in same frame

    const double base = g_base[i];
    const double c1 = g_c1[i], c2h = g_c2h[i];
    const float af = g_af[i], bf = g_bf[i];
    const unsigned vi = g_vuv[i], vn = g_vuv[i + 1];
    const float v48a = (float)(vi & 1),         v48b = (float)(vn & 1);
    const float v144a = (float)((vi >> 1) & 1), v144b = (float)((vn >> 1) & 1);
    const float v432a = (float)((vi >> 2) & 1), v432b = (float)((vn >> 2) & 1);

    float ph[4], trv[4], f0cv[4];
    #pragma unroll
    for (int r = 0; r < 4; r++) {
        const double jd = (double)(j0 + r);
        const double u = base + (jd + 1.0) * c1 + (jd * (jd + 1.0)) * c2h;
        ph[r] = (float)(u - floor(u));
        trv[r] = g_trans[j0 + r];
        f0cv[r] = af + (bf - af) * ((float)(j0 + r) * (1.0f / 480.0f));
    }

    float4 out;
    float* op = (float*)&out;
    #pragma unroll
    for (int r = 0; r < 4; r++) {
        float acc = 0.0f;
        acc += band_lookup(g_pr48, 48 * 1024, ph[r], trv[r], v48a, v48b);
        acc += band_lookup(g_pr144, 144 * 1024, ph[r], trv[r], v144a, v144b);
        acc += band_lookup(g_pr432, 432 * 1024, ph[r], trv[r], v432a, v432b);
        op[r] = acc * f0cv[r] * (1.0f / 48000.0f);
    }
    *(float4*)(g_p2x + s0) = out;
}

// ---------------- K4: radix-8 Stockham, 4 frames per 256-thread block ----------------
template<int N, int S>
__device__ __forceinline__ void step8(const float2* __restrict__ src, float2* __restrict__ dst,
                                      int t) {
    constexpr int N1 = N / 8;
    constexpr int M = 1024 / N;
    const int p = t / S;
    const int q = t - p * S;

    float2 x[8];
    #pragma unroll
    for (int r = 0; r < 8; r++) x[r] = src[PADI(q + S * (p + r * N1))];

    float2 ea = cadd(x[0], x[4]), eb = csub(x[0], x[4]);
    float2 ec = cadd(x[2], x[6]), ed = csub(x[2], x[6]);
    float2 E0 = cadd(ea, ec), E2 = csub(ea, ec);
    float2 E1 = csub(eb, jmul(ed)), E3 = cadd(eb, jmul(ed));

    float2 oa = cadd(x[1], x[5]), ob = csub(x[1], x[5]);
    float2 oc = cadd(x[3], x[7]), od = csub(x[3], x[7]);
    float2 O0 = cadd(oa, oc), O2 = csub(oa, oc);
    float2 O1 = csub(ob, jmul(od)), O3 = cadd(ob, jmul(od));

    const float C = 0.70710678118654752440f;
    float2 T1 = make_float2(C * (O1.x + O1.y), C * (O1.y - O1.x));
    float2 T2 = make_float2(O2.y, -O2.x);
    float2 T3 = make_float2(C * (O3.y - O3.x), -C * (O3.x + O3.y));

    float2 Y[8];
    Y[0] = cadd(E0, O0); Y[4] = csub(E0, O0);
    Y[1] = cadd(E1, T1); Y[5] = csub(E1, T1);
    Y[2] = cadd(E2, T2); Y[6] = csub(E2, T2);
    Y[3] = cadd(E3, T3); Y[7] = csub(E3, T3);

    if (N == 8) {
        #pragma unroll
        for (int r = 0; r < 8; r++) dst[PADI(q + S * (8 * p + r))] = Y[r];
    } else {
        const float2 w1 = __ldg(&g_tw[p * M]);
        const float2 w2 = cmul(w1, w1);
        const float2 w3 = cmul(w2, w1);
        const float2 w4 = cmul(w2, w2);
        const float2 w5 = cmul(w4, w1);
        const float2 w6 = cmul(w4, w2);
        const float2 w7 = cmul(w4, w3);
        dst[PADI(q + S * (8 * p + 0))] = Y[0];
        dst[PADI(q + S * (8 * p + 1))] = cmul(w1, Y[1]);
        dst[PADI(q + S * (8 * p + 2))] = cmul(w2, Y[2]);
        dst[PADI(q + S * (8 * p + 3))] = cmul(w3, Y[3]);
        dst[PADI(q + S * (8 * p + 4))] = cmul(w4, Y[4]);
        dst[PADI(q + S * (8 * p + 5))] = cmul(w5, Y[5]);
        dst[PADI(q + S * (8 * p + 6))] = cmul(w6, Y[6]);
        dst[PADI(q + S * (8 * p + 7))] = cmul(w7, Y[7]);
    }
}

__device__ __forceinline__ void fft512(float2* __restrict__ U, float2* __restrict__ V, int t) {
    step8<512, 1>(U, V, t);  __syncthreads();
    step8<64, 8>(V, U, t);   __syncthreads();
    step8<8, 64>(U, V, t);   __syncthreads();
}

#define FPB 4   /* frames per block */

__global__ void __launch_bounds__(64 * FPB) k_fft() {
    __shared__ float2 Ub[FPB][PADSZ];
    __shared__ float2 Vb[FPB][PADSZ];
    const int tid = threadIdx.x;
    const int sub = tid >> 6;            // which frame lane
    const int t = tid & 63;
    const int frame = blockIdx.x * FPB + sub;
    const bool valid = (frame < NSTFT);

    float2* U = Ub[sub];
    float2* V = Vb[sub];

    // load 1024 samples (reflect pad), window, pack even + i*odd -> 512 complex
    #pragma unroll
    for (int n0 = t; n0 < 512; n0 += 64) {
        float xe = 0.0f, xo = 0.0f;
        if (valid) {
            int ge = frame * HOP2XC - 512 + 2 * n0;
            if (ge >= 0 && ge + 1 < L2X) {
                float2 v = *(const float2*)(g_p2x + ge);   // aligned: ge even
                xe = v.x; xo = v.y;
            } else {
                int go = ge + 1;
                if (ge < 0) ge = -ge;
                if (ge >= L2X) ge = 2 * L2X - 2 - ge;
                if (go < 0) go = -go;
                if (go >= L2X) go = 2 * L2X - 2 - go;
                xe = g_p2x[ge];
                xo = g_p2x[go];
            }
            xe *= g_w1024[2 * n0];
            xo *= g_w1024[2 * n0 + 1];
        }
        U[PADI(n0)] = make_float2(xe, xo);
    }
    __syncthreads();

    fft512(U, V, t);            // Z in V

    // conj of hermitian-extended X[0..256] (imag dropped at DC/Nyquist), into U
    for (int j = t; j <= 256; j += 64) {
        const float2 Zj = V[PADI(j)];
        const float2 Zm = V[PADI((512 - j) & 511)];
        const float2 E = make_float2(0.5f * (Zj.x + Zm.x), 0.5f * (Zj.y - Zm.y));
        const float2 O = make_float2(0.5f * (Zj.y + Zm.y), -0.5f * (Zj.x - Zm.x));
        const float2 X = cadd(E, cmul(__ldg(&g_tw[j]), O));
        if (j == 0) {
            U[PADI(0)] = make_float2(X.x, 0.0f);
        } else if (j == 256) {
            U[PADI(256)] = make_float2(X.x, 0.0f);
        } else {
            U[PADI(j)] = make_float2(X.x, -X.y);
            U[PADI(512 - j)] = make_float2(X.x, X.y);
        }
    }
    __syncthreads();

    fft512(U, V, t);            // FFT(conj(B)) in V

    if (valid) {
        #pragma unroll
        for (int m = t; m < 512; m += 64) {
            g_ybuf[frame * 512 + m] = V[PADI(m)].x * (1.0f / 512.0f) * g_w512[m];
        }
    }
}

// ---------------- K5: deterministic OLA gather + env normalize ----------------
__global__ void k_ola(float* __restrict__ out) {
    int n = blockIdx.x * blockDim.x + threadIdx.x;
    if (n >= OUTLEN) return;
    const int s = n + 256;
    int tlo = (s >= 512) ? (s - 511 + 239) / 240 : 0;
    int thi = s / 240;
    if (thi > NFRAMES) thi = NFRAMES;
    float sig = 0.0f, env = 0.0f;
    for (int t = tlo; t <= thi; t++) {
        const int m = s - 240 * t;
        const float w = g_w512[m];
        sig += g_ybuf[t * 512 + m];
        env += w * w;
    }
    out[n] = (env > 1e-11f) ? (sig / env) : 0.0f;
}

// ---------------- launcher ----------------
extern "C" void kernel_launch(void* const* d_in, const int* in_sizes, int n_in,
                              void* d_out, int out_size) {
    const float* f0    = (const float*)d_in[0];
    const float* py48  = (const float*)d_in[1];
    const float* py144 = (const float*)d_in[2];
    const float* py432 = (const float*)d_in[3];
    float* out = (float*)d_out;
    (void)in_sizes; (void)n_in; (void)out_size;

    k_setup<<<1, 1024>>>();
    k_pairs<<<(LEN432 + 255) / 256, 256>>>(py48, py144, py432);
    k_frames<<<(NFRAMES + 255) / 256, 256>>>(f0);
    k_scan<<<1, 1024>>>();
    k_gen<<<L2X / 4 / 256, 256>>>();
    k_fft<<<(NSTFT + FPB - 1) / FPB, 64 * FPB>>>();
    k_ola<<<(OUTLEN + 255) / 256, 256>>>(out);
}

// round 6
// speedup vs baseline: 3.3952x; 1.0970x over previous
#include <cuda_runtime.h>
#include <math.h>

#define NFRAMES   16384
#define HOPC      240
#define HOP2XC    480
#define L2X       (NFRAMES*HOP2XC)      /* 7,864,320 */
#define NSTFT     (NFRAMES+1)           /* 16385 */
#define OUTLEN    (NFRAMES*HOPC)        /* 3,932,160 */
#define PI_D      3.14159265358979323846

#define LEN48   (48*1024+1)
#define LEN144  (144*1024+1)
#define LEN432  (432*1024+1)

#define NCHUNK  128
#define CHUNKSZ 128   /* NCHUNK*CHUNKSZ == NFRAMES */

// ---------------- static device scratch ----------------
__device__ float  g_p2x[L2X];
__device__ float  g_ybuf[NSTFT * 512];
__device__ double g_S[NFRAMES];
__device__ double g_ex[NFRAMES];              // exclusive prefix within chunk
__device__ double g_csum[NCHUNK];             // per-chunk sums
__device__ double g_cbase[NCHUNK];            // exclusive prefix of chunk sums
__device__ double g_base[NFRAMES];
__device__ double g_c1[NFRAMES];
__device__ double g_c2h[NFRAMES];
__device__ float  g_af[NFRAMES];
__device__ float  g_bf[NFRAMES];
__device__ unsigned char g_vuv[NFRAMES + 1];
__device__ float  g_w1024[1024];
__device__ float  g_w512[512];
__device__ float2 g_tw[1024];                 // exp(-2*pi*i*k/1024)
__device__ float  g_trans[HOP2XC];
__device__ float2 g_pr48[LEN48];              // {y[i], y[i+1]} pairs
__device__ float2 g_pr144[LEN144];
__device__ float2 g_pr432[LEN432];

// ---------------- helpers ----------------
__device__ __forceinline__ float2 cmul(float2 a, float2 b) {
    return make_float2(a.x * b.x - a.y * b.y, a.x * b.y + a.y * b.x);
}
__device__ __forceinline__ float2 cadd(float2 a, float2 b) { return make_float2(a.x + b.x, a.y + b.y); }
__device__ __forceinline__ float2 csub(float2 a, float2 b) { return make_float2(a.x - b.x, a.y - b.y); }
__device__ __forceinline__ float2 jmul(float2 a) { return make_float2(-a.y, a.x); }   // i*a

#define PADI(i) ((i) + ((i) >> 3))   /* pad every 8 float2 */
#define PADSZ   (512 + 64)

// 128-thread (4-warp) inclusive scan of one double per thread
__device__ __forceinline__ double block128_incl_scan(double s, double* warpsum) {
    const int t = threadIdx.x;
    const int lane = t & 31;
    const int wid = t >> 5;
    double v = s;
    #pragma unroll
    for (int off = 1; off < 32; off <<= 1) {
        double n = __shfl_up_sync(0xffffffffu, v, off);
        if (lane >= off) v += n;
    }
    if (lane == 31) warpsum[wid] = v;
    __syncthreads();
    if (t == 0) {
        double acc = 0.0;
        #pragma unroll
        for (int w = 0; w < 4; w++) { double x = warpsum[w]; warpsum[w] = acc; acc += x; }
    }
    __syncthreads();
    return v + warpsum[wid];
}

// ---------------- K0: tables (spread over blocks; fp64 trig) ----------------
__global__ void k_setup() {
    int t = blockIdx.x * blockDim.x + threadIdx.x;   // 1024 total
    g_w1024[t] = (float)(0.5 - 0.5 * cos(2.0 * PI_D * (double)t / 1024.0));
    double ang = -2.0 * PI_D * (double)t / 1024.0;
    g_tw[t] = make_float2((float)cos(ang), (float)sin(ang));
    if (t < 512) g_w512[t] = (float)(0.5 - 0.5 * cos(2.0 * PI_D * (double)t / 512.0));
    if (t < HOP2XC) {
        double s = sin(((double)t / (double)HOP2XC) * (PI_D * 0.5));
        g_trans[t] = (float)(s * s);
    }
}

// ---------------- K0b: build {y[i], y[i+1]} pair tables ----------------
__global__ void k_pairs(const float* __restrict__ py48, const float* __restrict__ py144,
                        const float* __restrict__ py432) {
    int i = blockIdx.x * blockDim.x + threadIdx.x;
    if (i < LEN48)  g_pr48[i]  = make_float2(py48[i],  py48[min(i + 1, LEN48 - 1)]);
    if (i < LEN144) g_pr144[i] = make_float2(py144[i], py144[min(i + 1, LEN144 - 1)]);
    if (i < LEN432) g_pr432[i] = make_float2(py432[i], py432[min(i + 1, LEN432 - 1)]);
}

// ---------------- K1: per-frame values ----------------
__global__ void k_frames(const float* __restrict__ f0) {
    int i = blockIdx.x * blockDim.x + threadIdx.x;
    if (i >= NFRAMES) return;
    double fi = (double)f0[i];
    double fn = (i + 1 < NFRAMES) ? (double)f0[i + 1] : 0.0;
    double a = (fi != 0.0) ? fi : fn;
    double b = (fn != 0.0) ? fn : fi;
    g_af[i] = (float)a;
    g_bf[i] = (float)b;
    g_c1[i] = a / 96000.0;
    g_c2h[i] = (b - a) / (2.0 * 480.0 * 96000.0);
    g_S[i] = (480.0 * a + (b - a) * (114960.0 / 480.0)) / 96000.0;
    unsigned char m = 0;
    if (fi >= 500.0 && fi < 1500.0) m |= 1;
    if (fi >= (24000.0 / 144.0) && fi < 500.0) m |= 2;
    if (fi >= (24000.0 / 432.0) && fi < (24000.0 / 144.0)) m |= 4;
    g_vuv[i] = m;
    if (i == NFRAMES - 1) g_vuv[NFRAMES] = 0;
}

// ---------------- K2a: per-chunk scan (128 blocks x 128 threads) ----------------
__global__ void __launch_bounds__(CHUNKSZ) k_scan1() {
    __shared__ double warpsum[4];
    const int i = blockIdx.x * CHUNKSZ + threadIdx.x;
    const double s = g_S[i];
    const double v = block128_incl_scan(s, warpsum);
    g_ex[i] = v - s;                      // exclusive within-chunk
    if (threadIdx.x == CHUNKSZ - 1) g_csum[blockIdx.x] = v;
}

// ---------------- K2b: scan chunk sums (1 block, 128 threads) ----------------
__global__ void __launch_bounds__(NCHUNK) k_scan2() {
    __shared__ double warpsum[4];
    const double s = g_csum[threadIdx.x];
    const double v = block128_incl_scan(s, warpsum);
    g_cbase[threadIdx.x] = v - s;         // exclusive across chunks
}

// ---------------- K2c: combine + frac ----------------
__global__ void k_scan3() {
    int i = blockIdx.x * blockDim.x + threadIdx.x;
    if (i >= NFRAMES) return;
    double base = g_cbase[i >> 7] + g_ex[i];
    g_base[i] = base - floor(base);
}

// ---------------- K3: excitation at 2x rate, 4 samples/thread, paired-table lookups ----
__device__ __forceinline__ float band_lookup(const float2* __restrict__ pair, int maxi,
                                             float phase, float tr, float v0, float v1) {
    if (v0 == 0.0f && v1 == 0.0f) return 0.0f;
    float mask = v0 + (v1 - v0) * tr;
    float idxf = phase * (float)maxi;
    idxf = fminf(fmaxf(idxf, 0.0f), (float)maxi);
    int lo = (int)floorf(idxf);
    float tt = idxf - (float)lo;
    float2 p = __ldg(pair + lo);
    return mask * (p.x + (p.y - p.x) * tt);
}

__global__ void __launch_bounds__(256) k_gen() {
    const int t = blockIdx.x * blockDim.x + threadIdx.x;   // L2X/4 threads
    const int s0 = t * 4;
    const int i = s0 / 480;
    const int j0 = s0 - i * 480;                            // all 4 in same frame

    const double base = g_base[i];
    const double c1 = g_c1[i], c2h = g_c2h[i];
    const float af = g_af[i], bf = g_bf[i];
    const unsigned vi = g_vuv[i], vn = g_vuv[i + 1];
    const float v48a = (float)(vi & 1),         v48b = (float)(vn & 1);
    const float v144a = (float)((vi >> 1) & 1), v144b = (float)((vn >> 1) & 1);
    const float v432a = (float)((vi >> 2) & 1), v432b = (float)((vn >> 2) & 1);

    float ph[4], trv[4], f0cv[4];
    #pragma unroll
    for (int r = 0; r < 4; r++) {
        const double jd = (double)(j0 + r);
        const double u = base + (jd + 1.0) * c1 + (jd * (jd + 1.0)) * c2h;
        ph[r] = (float)(u - floor(u));
        trv[r] = g_trans[j0 + r];
        f0cv[r] = af + (bf - af) * ((float)(j0 + r) * (1.0f / 480.0f));
    }

    float4 out;
    float* op = (float*)&out;
    #pragma unroll
    for (int r = 0; r < 4; r++) {
        float acc = 0.0f;
        acc += band_lookup(g_pr48, 48 * 1024, ph[r], trv[r], v48a, v48b);
        acc += band_lookup(g_pr144, 144 * 1024, ph[r], trv[r], v144a, v144b);
        acc += band_lookup(g_pr432, 432 * 1024, ph[r], trv[r], v432a, v432b);
        op[r] = acc * f0cv[r] * (1.0f / 48000.0f);
    }
    *(float4*)(g_p2x + s0) = out;
}

// ---------------- K4: radix-8 Stockham, 4 frames per 256-thread block ----------------
template<int N, int S>
__device__ __forceinline__ void step8(const float2* __restrict__ src, float2* __restrict__ dst,
                                      int t) {
    constexpr int N1 = N / 8;
    constexpr int M = 1024 / N;
    const int p = t / S;
    const int q = t - p * S;

    float2 x[8];
    #pragma unroll
    for (int r = 0; r < 8; r++) x[r] = src[PADI(q + S * (p + r * N1))];

    float2 ea = cadd(x[0], x[4]), eb = csub(x[0], x[4]);
    float2 ec = cadd(x[2], x[6]), ed = csub(x[2], x[6]);
    float2 E0 = cadd(ea, ec), E2 = csub(ea, ec);
    float2 E1 = csub(eb, jmul(ed)), E3 = cadd(eb, jmul(ed));

    float2 oa = cadd(x[1], x[5]), ob = csub(x[1], x[5]);
    float2 oc = cadd(x[3], x[7]), od = csub(x[3], x[7]);
    float2 O0 = cadd(oa, oc), O2 = csub(oa, oc);
    float2 O1 = csub(ob, jmul(od)), O3 = cadd(ob, jmul(od));

    const float C = 0.70710678118654752440f;
    float2 T1 = make_float2(C * (O1.x + O1.y), C * (O1.y - O1.x));
    float2 T2 = make_float2(O2.y, -O2.x);
    float2 T3 = make_float2(C * (O3.y - O3.x), -C * (O3.x + O3.y));

    float2 Y[8];
    Y[0] = cadd(E0, O0); Y[4] = csub(E0, O0);
    Y[1] = cadd(E1, T1); Y[5] = csub(E1, T1);
    Y[2] = cadd(E2, T2); Y[6] = csub(E2, T2);
    Y[3] = cadd(E3, T3); Y[7] = csub(E3, T3);

    if (N == 8) {
        #pragma unroll
        for (int r = 0; r < 8; r++) dst[PADI(q + S * (8 * p + r))] = Y[r];
    } else {
        const float2 w1 = __ldg(&g_tw[p * M]);
        const float2 w2 = cmul(w1, w1);
        const float2 w3 = cmul(w2, w1);
        const float2 w4 = cmul(w2, w2);
        const float2 w5 = cmul(w4, w1);
        const float2 w6 = cmul(w4, w2);
        const float2 w7 = cmul(w4, w3);
        dst[PADI(q + S * (8 * p + 0))] = Y[0];
        dst[PADI(q + S * (8 * p + 1))] = cmul(w1, Y[1]);
        dst[PADI(q + S * (8 * p + 2))] = cmul(w2, Y[2]);
        dst[PADI(q + S * (8 * p + 3))] = cmul(w3, Y[3]);
        dst[PADI(q + S * (8 * p + 4))] = cmul(w4, Y[4]);
        dst[PADI(q + S * (8 * p + 5))] = cmul(w5, Y[5]);
        dst[PADI(q + S * (8 * p + 6))] = cmul(w6, Y[6]);
        dst[PADI(q + S * (8 * p + 7))] = cmul(w7, Y[7]);
    }
}

__device__ __forceinline__ void fft512(float2* __restrict__ U, float2* __restrict__ V, int t) {
    step8<512, 1>(U, V, t);  __syncthreads();
    step8<64, 8>(V, U, t);   __syncthreads();
    step8<8, 64>(U, V, t);   __syncthreads();
}

#define FPB 4   /* frames per block */

__global__ void __launch_bounds__(64 * FPB) k_fft() {
    __shared__ float2 Ub[FPB][PADSZ];
    __shared__ float2 Vb[FPB][PADSZ];
    const int tid = threadIdx.x;
    const int sub = tid >> 6;            // which frame lane
    const int t = tid & 63;
    const int frame = blockIdx.x * FPB + sub;
    const bool valid = (frame < NSTFT);

    float2* U = Ub[sub];
    float2* V = Vb[sub];

    // load 1024 samples (reflect pad), window, pack even + i*odd -> 512 complex
    #pragma unroll
    for (int n0 = t; n0 < 512; n0 += 64) {
        float xe = 0.0f, xo = 0.0f;
        if (valid) {
            int ge = frame * HOP2XC - 512 + 2 * n0;
            if (ge >= 0 && ge + 1 < L2X) {
                float2 v = *(const float2*)(g_p2x + ge);   // aligned: ge even
                xe = v.x; xo = v.y;
            } else {
                int go = ge + 1;
                if (ge < 0) ge = -ge;
                if (ge >= L2X) ge = 2 * L2X - 2 - ge;
                if (go < 0) go = -go;
                if (go >= L2X) go = 2 * L2X - 2 - go;
                xe = g_p2x[ge];
                xo = g_p2x[go];
            }
            xe *= g_w1024[2 * n0];
            xo *= g_w1024[2 * n0 + 1];
        }
        U[PADI(n0)] = make_float2(xe, xo);
    }
    __syncthreads();

    fft512(U, V, t);            // Z in V

    // conj of hermitian-extended X[0..256] (imag dropped at DC/Nyquist), into U
    for (int j = t; j <= 256; j += 64) {
        const float2 Zj = V[PADI(j)];
        const float2 Zm = V[PADI((512 - j) & 511)];
        const float2 E = make_float2(0.5f * (Zj.x + Zm.x), 0.5f * (Zj.y - Zm.y));
        const float2 O = make_float2(0.5f * (Zj.y + Zm.y), -0.5f * (Zj.x - Zm.x));
        const float2 X = cadd(E, cmul(__ldg(&g_tw[j]), O));
        if (j == 0) {
            U[PADI(0)] = make_float2(X.x, 0.0f);
        } else if (j == 256) {
            U[PADI(256)] = make_float2(X.x, 0.0f);
        } else {
            U[PADI(j)] = make_float2(X.x, -X.y);
            U[PADI(512 - j)] = make_float2(X.x, X.y);
        }
    }
    __syncthreads();

    fft512(U, V, t);            // FFT(conj(B)) in V

    if (valid) {
        #pragma unroll
        for (int m = t; m < 512; m += 64) {
            g_ybuf[frame * 512 + m] = V[PADI(m)].x * (1.0f / 512.0f) * g_w512[m];
        }
    }
}

// ---------------- K5: deterministic OLA gather + env normalize ----------------
__global__ void k_ola(float* __restrict__ out) {
    int n = blockIdx.x * blockDim.x + threadIdx.x;
    if (n >= OUTLEN) return;
    const int s = n + 256;
    int tlo = (s >= 512) ? (s - 511 + 239) / 240 : 0;
    int thi = s / 240;
    if (thi > NFRAMES) thi = NFRAMES;
    float sig = 0.0f, env = 0.0f;
    for (int t = tlo; t <= thi; t++) {
        const int m = s - 240 * t;
        const float w = g_w512[m];
        sig += g_ybuf[t * 512 + m];
        env += w * w;
    }
    out[n] = (env > 1e-11f) ? (sig / env) : 0.0f;
}

// ---------------- launcher ----------------
extern "C" void kernel_launch(void* const* d_in, const int* in_sizes, int n_in,
                              void* d_out, int out_size) {
    const float* f0    = (const float*)d_in[0];
    const float* py48  = (const float*)d_in[1];
    const float* py144 = (const float*)d_in[2];
    const float* py432 = (const float*)d_in[3];
    float* out = (float*)d_out;
    (void)in_sizes; (void)n_in; (void)out_size;

    k_setup<<<8, 128>>>();
    k_pairs<<<(LEN432 + 255) / 256, 256>>>(py48, py144, py432);
    k_frames<<<(NFRAMES + 255) / 256, 256>>>(f0);
    k_scan1<<<NCHUNK, CHUNKSZ>>>();
    k_scan2<<<1, NCHUNK>>>();
    k_scan3<<<(NFRAMES + 255) / 256, 256>>>();
    k_gen<<<L2X / 4 / 256, 256>>>();
    k_fft<<<(NSTFT + FPB - 1) / FPB, 64 * FPB>>>();
    k_ola<<<(OUTLEN + 255) / 256, 256>>>(out);
}

// round 7
// speedup vs baseline: 3.6390x; 1.0718x over previous
#include <cuda_runtime.h>
#include <math.h>

#define NFRAMES   16384
#define HOPC      240
#define HOP2XC    480
#define L2X       (NFRAMES*HOP2XC)      /* 7,864,320 */
#define NSTFT     (NFRAMES+1)           /* 16385 */
#define OUTLEN    (NFRAMES*HOPC)        /* 3,932,160 */
#define PI_D      3.14159265358979323846

#define LEN48   (48*1024+1)
#define LEN144  (144*1024+1)
#define LEN432  (432*1024+1)

#define NCHUNK  128
#define CHUNKSZ 128   /* NCHUNK*CHUNKSZ == NFRAMES */

// ---------------- static device scratch ----------------
__device__ float  g_p2x[L2X];
__device__ float  g_ybuf[NSTFT * 512];
__device__ double g_S[NFRAMES];
__device__ double g_ex[NFRAMES];
__device__ double g_csum[NCHUNK];
__device__ double g_cbase[NCHUNK];
__device__ double g_base[NFRAMES];
__device__ double g_c1[NFRAMES];
__device__ double g_c2h[NFRAMES];
__device__ float  g_af[NFRAMES];
__device__ float  g_bf[NFRAMES];
__device__ unsigned char g_vuv[NFRAMES + 1];
__device__ float  g_w1024[1024];
__device__ float  g_w512[512];
__device__ float2 g_tw[1024];                 // exp(-2*pi*i*k/1024)
__device__ float  g_trans[HOP2XC];
__device__ float2 g_pr48[LEN48];
__device__ float2 g_pr144[LEN144];
__device__ float2 g_pr432[LEN432];

// ---------------- helpers ----------------
__device__ __forceinline__ float2 cmul(float2 a, float2 b) {
    return make_float2(a.x * b.x - a.y * b.y, a.x * b.y + a.y * b.x);
}
__device__ __forceinline__ float2 cadd(float2 a, float2 b) { return make_float2(a.x + b.x, a.y + b.y); }
__device__ __forceinline__ float2 csub(float2 a, float2 b) { return make_float2(a.x - b.x, a.y - b.y); }
__device__ __forceinline__ float2 jmul(float2 a) { return make_float2(-a.y, a.x); }   // i*a

#define PADI(i) ((i) + ((i) >> 3))   /* pad every 8 float2 */
#define PADSZ   (512 + 64)

// 128-thread (4-warp) inclusive scan of one double per thread
__device__ __forceinline__ double block128_incl_scan(double s, double* warpsum) {
    const int t = threadIdx.x;
    const int lane = t & 31;
    const int wid = t >> 5;
    double v = s;
    #pragma unroll
    for (int off = 1; off < 32; off <<= 1) {
        double n = __shfl_up_sync(0xffffffffu, v, off);
        if (lane >= off) v += n;
    }
    if (lane == 31) warpsum[wid] = v;
    __syncthreads();
    if (t == 0) {
        double acc = 0.0;
        #pragma unroll
        for (int w = 0; w < 4; w++) { double x = warpsum[w]; warpsum[w] = acc; acc += x; }
    }
    __syncthreads();
    return v + warpsum[wid];
}

// ---------------- K-init: fused setup + pair tables + per-frame values ----------------
__global__ void k_init(const float* __restrict__ f0,
                       const float* __restrict__ py48, const float* __restrict__ py144,
                       const float* __restrict__ py432) {
    int i = blockIdx.x * blockDim.x + threadIdx.x;
    if (i < LEN48)  g_pr48[i]  = make_float2(py48[i],  py48[min(i + 1, LEN48 - 1)]);
    if (i < LEN144) g_pr144[i] = make_float2(py144[i], py144[min(i + 1, LEN144 - 1)]);
    if (i < LEN432) g_pr432[i] = make_float2(py432[i], py432[min(i + 1, LEN432 - 1)]);
    if (i < 1024) {
        g_w1024[i] = (float)(0.5 - 0.5 * cos(2.0 * PI_D * (double)i / 1024.0));
        double ang = -2.0 * PI_D * (double)i / 1024.0;
        g_tw[i] = make_float2((float)cos(ang), (float)sin(ang));
        if (i < 512) g_w512[i] = (float)(0.5 - 0.5 * cos(2.0 * PI_D * (double)i / 512.0));
        if (i < HOP2XC) {
            double s = sin(((double)i / (double)HOP2XC) * (PI_D * 0.5));
            g_trans[i] = (float)(s * s);
        }
    }
    if (i < NFRAMES) {
        double fi = (double)f0[i];
        double fn = (i + 1 < NFRAMES) ? (double)f0[i + 1] : 0.0;
        double a = (fi != 0.0) ? fi : fn;
        double b = (fn != 0.0) ? fn : fi;
        g_af[i] = (float)a;
        g_bf[i] = (float)b;
        g_c1[i] = a / 96000.0;
        g_c2h[i] = (b - a) / (2.0 * 480.0 * 96000.0);
        g_S[i] = (480.0 * a + (b - a) * (114960.0 / 480.0)) / 96000.0;
        unsigned char m = 0;
        if (fi >= 500.0 && fi < 1500.0) m |= 1;
        if (fi >= (24000.0 / 144.0) && fi < 500.0) m |= 2;
        if (fi >= (24000.0 / 432.0) && fi < (24000.0 / 144.0)) m |= 4;
        g_vuv[i] = m;
        if (i == NFRAMES - 1) g_vuv[NFRAMES] = 0;
    }
}

// ---------------- K2a/b/c: distributed frame scan ----------------
__global__ void __launch_bounds__(CHUNKSZ) k_scan1() {
    __shared__ double warpsum[4];
    const int i = blockIdx.x * CHUNKSZ + threadIdx.x;
    const double s = g_S[i];
    const double v = block128_incl_scan(s, warpsum);
    g_ex[i] = v - s;
    if (threadIdx.x == CHUNKSZ - 1) g_csum[blockIdx.x] = v;
}

__global__ void __launch_bounds__(NCHUNK) k_scan2() {
    __shared__ double warpsum[4];
    const double s = g_csum[threadIdx.x];
    const double v = block128_incl_scan(s, warpsum);
    g_cbase[threadIdx.x] = v - s;
}

__global__ void k_scan3() {
    int i = blockIdx.x * blockDim.x + threadIdx.x;
    if (i >= NFRAMES) return;
    double base = g_cbase[i >> 7] + g_ex[i];
    g_base[i] = base - floor(base);
}

// ---------------- K3: excitation at 2x rate ----------------
__device__ __forceinline__ float band_lookup(const float2* __restrict__ pair, int maxi,
                                             float phase, float tr, float v0, float v1) {
    if (v0 == 0.0f && v1 == 0.0f) return 0.0f;
    float mask = v0 + (v1 - v0) * tr;
    float idxf = phase * (float)maxi;
    idxf = fminf(fmaxf(idxf, 0.0f), (float)maxi);
    int lo = (int)floorf(idxf);
    float tt = idxf - (float)lo;
    float2 p = __ldg(pair + lo);
    return mask * (p.x + (p.y - p.x) * tt);
}

__global__ void __launch_bounds__(256) k_gen() {
    const int t = blockIdx.x * blockDim.x + threadIdx.x;
    const int s0 = t * 4;
    const int i = s0 / 480;
    const int j0 = s0 - i * 480;

    const double base = g_base[i];
    const double c1 = g_c1[i], c2h = g_c2h[i];
    const float af = g_af[i], bf = g_bf[i];
    const unsigned vi = g_vuv[i], vn = g_vuv[i + 1];
    const float v48a = (float)(vi & 1),         v48b = (float)(vn & 1);
    const float v144a = (float)((vi >> 1) & 1), v144b = (float)((vn >> 1) & 1);
    const float v432a = (float)((vi >> 2) & 1), v432b = (float)((vn >> 2) & 1);

    float ph[4], trv[4], f0cv[4];
    #pragma unroll
    for (int r = 0; r < 4; r++) {
        const double jd = (double)(j0 + r);
        const double u = base + (jd + 1.0) * c1 + (jd * (jd + 1.0)) * c2h;
        ph[r] = (float)(u - floor(u));
        trv[r] = g_trans[j0 + r];
        f0cv[r] = af + (bf - af) * ((float)(j0 + r) * (1.0f / 480.0f));
    }

    float4 out;
    float* op = (float*)&out;
    #pragma unroll
    for (int r = 0; r < 4; r++) {
        float acc = 0.0f;
        acc += band_lookup(g_pr48, 48 * 1024, ph[r], trv[r], v48a, v48b);
        acc += band_lookup(g_pr144, 144 * 1024, ph[r], trv[r], v144a, v144b);
        acc += band_lookup(g_pr432, 432 * 1024, ph[r], trv[r], v432a, v432b);
        op[r] = acc * f0cv[r] * (1.0f / 48000.0f);
    }
    *(float4*)(g_p2x + s0) = out;
}

// ---------------- K4: STFT->truncate->ISTFT via FFT512 + packed IFFT256 ----------------
template<int N, int S>
__device__ __forceinline__ void step8(const float2* __restrict__ src, float2* __restrict__ dst,
                                      int t) {
    constexpr int N1 = N / 8;
    constexpr int M = 1024 / N;
    const int p = t / S;
    const int q = t - p * S;

    float2 x[8];
    #pragma unroll
    for (int r = 0; r < 8; r++) x[r] = src[PADI(q + S * (p + r * N1))];

    float2 ea = cadd(x[0], x[4]), eb = csub(x[0], x[4]);
    float2 ec = cadd(x[2], x[6]), ed = csub(x[2], x[6]);
    float2 E0 = cadd(ea, ec), E2 = csub(ea, ec);
    float2 E1 = csub(eb, jmul(ed)), E3 = cadd(eb, jmul(ed));

    float2 oa = cadd(x[1], x[5]), ob = csub(x[1], x[5]);
    float2 oc = cadd(x[3], x[7]), od = csub(x[3], x[7]);
    float2 O0 = cadd(oa, oc), O2 = csub(oa, oc);
    float2 O1 = csub(ob, jmul(od)), O3 = cadd(ob, jmul(od));

    const float C = 0.70710678118654752440f;
    float2 T1 = make_float2(C * (O1.x + O1.y), C * (O1.y - O1.x));
    float2 T2 = make_float2(O2.y, -O2.x);
    float2 T3 = make_float2(C * (O3.y - O3.x), -C * (O3.x + O3.y));

    float2 Y[8];
    Y[0] = cadd(E0, O0); Y[4] = csub(E0, O0);
    Y[1] = cadd(E1, T1); Y[5] = csub(E1, T1);
    Y[2] = cadd(E2, T2); Y[6] = csub(E2, T2);
    Y[3] = cadd(E3, T3); Y[7] = csub(E3, T3);

    if (N == 8) {
        #pragma unroll
        for (int r = 0; r < 8; r++) dst[PADI(q + S * (8 * p + r))] = Y[r];
    } else {
        const float2 w1 = __ldg(&g_tw[p * M]);
        const float2 w2 = cmul(w1, w1);
        const float2 w3 = cmul(w2, w1);
        const float2 w4 = cmul(w2, w2);
        const float2 w5 = cmul(w4, w1);
        const float2 w6 = cmul(w4, w2);
        const float2 w7 = cmul(w4, w3);
        dst[PADI(q + S * (8 * p + 0))] = Y[0];
        dst[PADI(q + S * (8 * p + 1))] = cmul(w1, Y[1]);
        dst[PADI(q + S * (8 * p + 2))] = cmul(w2, Y[2]);
        dst[PADI(q + S * (8 * p + 3))] = cmul(w3, Y[3]);
        dst[PADI(q + S * (8 * p + 4))] = cmul(w4, Y[4]);
        dst[PADI(q + S * (8 * p + 5))] = cmul(w5, Y[5]);
        dst[PADI(q + S * (8 * p + 6))] = cmul(w6, Y[6]);
        dst[PADI(q + S * (8 * p + 7))] = cmul(w7, Y[7]);
    }
}

// radix-4 Stockham step for the 256-pt FFT (64 threads = 64 butterflies)
template<int N, int S>
__device__ __forceinline__ void step4(const float2* __restrict__ src, float2* __restrict__ dst,
                                      int t) {
    constexpr int N1 = N / 4;
    constexpr int M = 1024 / N;
    const int p = t / S;
    const int q = t - p * S;
    float2 a = src[PADI(q + S * p)];
    float2 b = src[PADI(q + S * (p + N1))];
    float2 c = src[PADI(q + S * (p + 2 * N1))];
    float2 d = src[PADI(q + S * (p + 3 * N1))];
    float2 apc = cadd(a, c), amc = csub(a, c);
    float2 bpd = cadd(b, d), jbmd = jmul(csub(b, d));
    float2 Y0 = cadd(apc, bpd);
    float2 Y1 = csub(amc, jbmd);
    float2 Y2 = csub(apc, bpd);
    float2 Y3 = cadd(amc, jbmd);
    if (N == 4) {
        dst[PADI(q + S * (4 * p + 0))] = Y0;
        dst[PADI(q + S * (4 * p + 1))] = Y1;
        dst[PADI(q + S * (4 * p + 2))] = Y2;
        dst[PADI(q + S * (4 * p + 3))] = Y3;
    } else {
        const float2 w1 = __ldg(&g_tw[p * M]);
        const float2 w2 = cmul(w1, w1);
        const float2 w3 = cmul(w2, w1);
        dst[PADI(q + S * (4 * p + 0))] = Y0;
        dst[PADI(q + S * (4 * p + 1))] = cmul(w1, Y1);
        dst[PADI(q + S * (4 * p + 2))] = cmul(w2, Y2);
        dst[PADI(q + S * (4 * p + 3))] = cmul(w3, Y3);
    }
}

#define FPB 4   /* frames per block */

__global__ void __launch_bounds__(64 * FPB) k_fft() {
    __shared__ float2 Ub[FPB][PADSZ];
    __shared__ float2 Vb[FPB][PADSZ];
    const int tid = threadIdx.x;
    const int sub = tid >> 6;
    const int t = tid & 63;
    const int frame = blockIdx.x * FPB + sub;
    const bool valid = (frame < NSTFT);

    float2* U = Ub[sub];
    float2* V = Vb[sub];

    // load 1024 samples (reflect pad), window, pack even + i*odd -> 512 complex
    #pragma unroll
    for (int n0 = t; n0 < 512; n0 += 64) {
        float xe = 0.0f, xo = 0.0f;
        if (valid) {
            int ge = frame * HOP2XC - 512 + 2 * n0;
            if (ge >= 0 && ge + 1 < L2X) {
                float2 v = *(const float2*)(g_p2x + ge);
                xe = v.x; xo = v.y;
            } else {
                int go = ge + 1;
                if (ge < 0) ge = -ge;
                if (ge >= L2X) ge = 2 * L2X - 2 - ge;
                if (go < 0) go = -go;
                if (go >= L2X) go = 2 * L2X - 2 - go;
                xe = g_p2x[ge];
                xo = g_p2x[go];
            }
            xe *= g_w1024[2 * n0];
            xo *= g_w1024[2 * n0 + 1];
        }
        U[PADI(n0)] = make_float2(xe, xo);
    }
    __syncthreads();

    // forward 512-pt FFT (3 radix-8 stages): result Z in V
    step8<512, 1>(U, V, t);  __syncthreads();
    step8<64, 8>(V, U, t);   __syncthreads();
    step8<8, 64>(U, V, t);   __syncthreads();

    // Fused: unpack real-FFT bins X[0..256], build irfft-256 packing
    // z[j] = Ev[j] + i*Od[j]; write w[j] = conj(z[j]) into U[0..255]
    for (int j = t; j <= 128; j += 64) {
        const float2 Zj = V[PADI(j)];
        const float2 Zmj = V[PADI((512 - j) & 511)];
        float2 E = make_float2(0.5f * (Zj.x + Zmj.x), 0.5f * (Zj.y - Zmj.y));
        float2 O = make_float2(0.5f * (Zj.y + Zmj.y), -0.5f * (Zj.x - Zmj.x));
        float2 Xa = cadd(E, cmul(__ldg(&g_tw[j]), O));
        if (j == 0) {
            const float X0r = Xa.x;                 // Re X[0]
            const float X256r = V[PADI(256)].x;     // Re X[256]
            // z[0] = (X0r+X256r)/2 + i*(X0r-X256r)/2 ; store conj
            U[PADI(0)] = make_float2(0.5f * (X0r + X256r), -0.5f * (X0r - X256r));
        } else {
            const int jp = 256 - j;
            const float2 Zk = V[PADI(jp)];
            const float2 Zmk = V[PADI(256 + j)];
            float2 E2 = make_float2(0.5f * (Zk.x + Zmk.x), 0.5f * (Zk.y - Zmk.y));
            float2 O2 = make_float2(0.5f * (Zk.y + Zmk.y), -0.5f * (Zk.x - Zmk.x));
            float2 Xb = cadd(E2, cmul(__ldg(&g_tw[jp]), O2));

            const float2 t2 = __ldg(&g_tw[2 * j]);         // e^{-2pi i j/512}
            const float2 tp = make_float2(t2.x, -t2.y);    // e^{+2pi i j/512}
            const float2 tpn = make_float2(-t2.x, -t2.y);  // e^{+2pi i (256-j)/512}

            // z[j] = 0.5*(Xa + conj(Xb)) + 0.5*i*tp*(Xa - conj(Xb))
            float2 S1 = make_float2(Xa.x + Xb.x, Xa.y - Xb.y);
            float2 D1 = make_float2(Xa.x - Xb.x, Xa.y + Xb.y);
            float2 zt = jmul(cmul(tp, D1));
            float2 zj = make_float2(0.5f * (S1.x + zt.x), 0.5f * (S1.y + zt.y));
            U[PADI(j)] = make_float2(zj.x, -zj.y);

            // z[256-j] = 0.5*(Xb + conj(Xa)) + 0.5*i*tpn*(Xb - conj(Xa))
            float2 S2 = make_float2(Xb.x + Xa.x, Xb.y - Xa.y);
            float2 D2 = make_float2(Xb.x - Xa.x, Xb.y + Xa.y);
            float2 zt2 = jmul(cmul(tpn, D2));
            float2 zp = make_float2(0.5f * (S2.x + zt2.x), 0.5f * (S2.y + zt2.y));
            U[PADI(jp)] = make_float2(zp.x, -zp.y);
        }
    }
    __syncthreads();

    // 256-pt forward FFT of conj(z) (4 radix-4 stages): result in U
    step4<256, 1>(U, V, t);  __syncthreads();
    step4<64, 4>(V, U, t);   __syncthreads();
    step4<16, 16>(U, V, t);  __syncthreads();
    step4<4, 64>(V, U, t);   __syncthreads();

    // y[2m] = Re(c)/256 * w512[2m]; y[2m+1] = -Im(c)/256 * w512[2m+1]
    if (valid) {
        #pragma unroll
        for (int m = t; m < 256; m += 64) {
            const float2 c = U[PADI(m)];
            float2 o;
            o.x = c.x * (1.0f / 256.0f) * g_w512[2 * m];
            o.y = -c.y * (1.0f / 256.0f) * g_w512[2 * m + 1];
            *(float2*)(g_ybuf + frame * 512 + 2 * m) = o;
        }
    }
}

// ---------------- K5: deterministic OLA gather + env normalize ----------------
__global__ void k_ola(float* __restrict__ out) {
    int n = blockIdx.x * blockDim.x + threadIdx.x;
    if (n >= OUTLEN) return;
    const int s = n + 256;
    int tlo = (s >= 512) ? (s - 511 + 239) / 240 : 0;
    int thi = s / 240;
    if (thi > NFRAMES) thi = NFRAMES;
    float sig = 0.0f, env = 0.0f;
    for (int t = tlo; t <= thi; t++) {
        const int m = s - 240 * t;
        const float w = g_w512[m];
        sig += g_ybuf[t * 512 + m];
        env += w * w;
    }
    out[n] = (env > 1e-11f) ? (sig / env) : 0.0f;
}

// ---------------- launcher ----------------
extern "C" void kernel_launch(void* const* d_in, const int* in_sizes, int n_in,
                              void* d_out, int out_size) {
    const float* f0    = (const float*)d_in[0];
    const float* py48  = (const float*)d_in[1];
    const float* py144 = (const float*)d_in[2];
    const float* py432 = (const float*)d_in[3];
    float* out = (float*)d_out;
    (void)in_sizes; (void)n_in; (void)out_size;

    k_init<<<(LEN432 + 255) / 256, 256>>>(f0, py48, py144, py432);
    k_scan1<<<NCHUNK, CHUNKSZ>>>();
    k_scan2<<<1, NCHUNK>>>();
    k_scan3<<<(NFRAMES + 255) / 256, 256>>>();
    k_gen<<<L2X / 4 / 256, 256>>>();
    k_fft<<<(NSTFT + FPB - 1) / FPB, 64 * FPB>>>();
    k_ola<<<(OUTLEN + 255) / 256, 256>>>(out);
}

// round 8
// speedup vs baseline: 3.8620x; 1.0613x over previous
#include <cuda_runtime.h>
#include <math.h>

#define NFRAMES   16384
#define HOPC      240
#define HOP2XC    480
#define L2X       (NFRAMES*HOP2XC)      /* 7,864,320 */
#define NSTFT     (NFRAMES+1)           /* 16385 */
#define OUTLEN    (NFRAMES*HOPC)        /* 3,932,160 */
#define PI_D      3.14159265358979323846

#define LEN48   (48*1024+1)
#define LEN144  (144*1024+1)
#define LEN432  (432*1024+1)

#define NCHUNK  128
#define CHUNKSZ 128   /* NCHUNK*CHUNKSZ == NFRAMES */

// ---------------- static device scratch ----------------
__device__ float  g_p2x[L2X];
__device__ float  g_ybuf[NSTFT * 512];
__device__ double g_S[NFRAMES];
__device__ double g_ex[NFRAMES];
__device__ double g_csum[NCHUNK];
__device__ double g_cbase[NCHUNK];
__device__ double g_c1[NFRAMES];
__device__ double g_c2h[NFRAMES];
__device__ float  g_af[NFRAMES];
__device__ float  g_bf[NFRAMES];
__device__ unsigned char g_vuv[NFRAMES + 1];
__device__ float  g_w1024[1024];
__device__ float  g_w512[512];
__device__ float  g_ienv[240];                // 1/env for interior samples, by s mod 240
__device__ float2 g_tw[1024];                 // exp(-2*pi*i*k/1024)
__device__ float  g_trans[HOP2XC];
__device__ float2 g_pr48[LEN48];
__device__ float2 g_pr144[LEN144];
__device__ float2 g_pr432[LEN432];

// ---------------- helpers ----------------
__device__ __forceinline__ float2 cmul(float2 a, float2 b) {
    return make_float2(a.x * b.x - a.y * b.y, a.x * b.y + a.y * b.x);
}
__device__ __forceinline__ float2 cadd(float2 a, float2 b) { return make_float2(a.x + b.x, a.y + b.y); }
__device__ __forceinline__ float2 csub(float2 a, float2 b) { return make_float2(a.x - b.x, a.y - b.y); }
__device__ __forceinline__ float2 jmul(float2 a) { return make_float2(-a.y, a.x); }   // i*a

#define PADI(i) ((i) + ((i) >> 3))   /* pad every 8 float2 */
#define PADSZ   (512 + 64)

__device__ __forceinline__ float hannf512(int n) {
    return (float)(0.5 - 0.5 * cos(2.0 * PI_D * (double)n / 512.0));
}

// 128-thread (4-warp) inclusive scan of one double per thread
__device__ __forceinline__ double block128_incl_scan(double s, double* warpsum) {
    const int t = threadIdx.x;
    const int lane = t & 31;
    const int wid = t >> 5;
    double v = s;
    #pragma unroll
    for (int off = 1; off < 32; off <<= 1) {
        double n = __shfl_up_sync(0xffffffffu, v, off);
        if (lane >= off) v += n;
    }
    if (lane == 31) warpsum[wid] = v;
    __syncthreads();
    if (t == 0) {
        double acc = 0.0;
        #pragma unroll
        for (int w = 0; w < 4; w++) { double x = warpsum[w]; warpsum[w] = acc; acc += x; }
    }
    __syncthreads();
    return v + warpsum[wid];
}

// ---------------- K-init: fused setup + pair tables + per-frame values ----------------
__global__ void k_init(const float* __restrict__ f0,
                       const float* __restrict__ py48, const float* __restrict__ py144,
                       const float* __restrict__ py432) {
    int i = blockIdx.x * blockDim.x + threadIdx.x;
    if (i < LEN48)  g_pr48[i]  = make_float2(py48[i],  py48[min(i + 1, LEN48 - 1)]);
    if (i < LEN144) g_pr144[i] = make_float2(py144[i], py144[min(i + 1, LEN144 - 1)]);
    if (i < LEN432) g_pr432[i] = make_float2(py432[i], py432[min(i + 1, LEN432 - 1)]);
    if (i < 1024) {
        g_w1024[i] = (float)(0.5 - 0.5 * cos(2.0 * PI_D * (double)i / 1024.0));
        double ang = -2.0 * PI_D * (double)i / 1024.0;
        g_tw[i] = make_float2((float)cos(ang), (float)sin(ang));
        if (i < 512) g_w512[i] = hannf512(i);
        if (i < HOP2XC) {
            double s = sin(((double)i / (double)HOP2XC) * (PI_D * 0.5));
            g_trans[i] = (float)(s * s);
        }
        if (i < 240) {
            // env(r) = w512[r]^2 + w512[r+240]^2 + (r<=31 ? w512[r+480]^2 : 0)
            float w0 = hannf512(i), w1 = hannf512(i + 240);
            float env = ((i <= 31) ? hannf512(i + 480) * hannf512(i + 480) : 0.0f)
                        + w1 * w1 + w0 * w0;
            g_ienv[i] = 1.0f / env;
        }
    }
    if (i < NFRAMES) {
        double fi = (double)f0[i];
        double fn = (i + 1 < NFRAMES) ? (double)f0[i + 1] : 0.0;
        double a = (fi != 0.0) ? fi : fn;
        double b = (fn != 0.0) ? fn : fi;
        g_af[i] = (float)a;
        g_bf[i] = (float)b;
        g_c1[i] = a / 96000.0;
        g_c2h[i] = (b - a) / (2.0 * 480.0 * 96000.0);
        g_S[i] = (480.0 * a + (b - a) * (114960.0 / 480.0)) / 96000.0;
        unsigned char m = 0;
        if (fi >= 500.0 && fi < 1500.0) m |= 1;
        if (fi >= (24000.0 / 144.0) && fi < 500.0) m |= 2;
        if (fi >= (24000.0 / 432.0) && fi < (24000.0 / 144.0)) m |= 4;
        g_vuv[i] = m;
        if (i == NFRAMES - 1) g_vuv[NFRAMES] = 0;
    }
}

// ---------------- K2a/b: distributed frame scan ----------------
__global__ void __launch_bounds__(CHUNKSZ) k_scan1() {
    __shared__ double warpsum[4];
    const int i = blockIdx.x * CHUNKSZ + threadIdx.x;
    const double s = g_S[i];
    const double v = block128_incl_scan(s, warpsum);
    g_ex[i] = v - s;
    if (threadIdx.x == CHUNKSZ - 1) g_csum[blockIdx.x] = v;
}

__global__ void __launch_bounds__(NCHUNK) k_scan2() {
    __shared__ double warpsum[4];
    const double s = g_csum[threadIdx.x];
    const double v = block128_incl_scan(s, warpsum);
    g_cbase[threadIdx.x] = v - s;
}

// ---------------- K3: excitation at 2x rate (base computed inline) ----------------
__device__ __forceinline__ float band_lookup(const float2* __restrict__ pair, int maxi,
                                             float phase, float tr, float v0, float v1) {
    if (v0 == 0.0f && v1 == 0.0f) return 0.0f;
    float mask = v0 + (v1 - v0) * tr;
    float idxf = phase * (float)maxi;
    idxf = fminf(fmaxf(idxf, 0.0f), (float)maxi);
    int lo = (int)floorf(idxf);
    float tt = idxf - (float)lo;
    float2 p = __ldg(pair + lo);
    return mask * (p.x + (p.y - p.x) * tt);
}

__global__ void __launch_bounds__(256) k_gen() {
    const int t = blockIdx.x * blockDim.x + threadIdx.x;
    const int s0 = t * 4;
    const int i = s0 / 480;
    const int j0 = s0 - i * 480;

    const double base0 = g_cbase[i >> 7] + g_ex[i];
    const double base = base0 - floor(base0);
    const double c1 = g_c1[i], c2h = g_c2h[i];
    const float af = g_af[i], bf = g_bf[i];
    const unsigned vi = g_vuv[i], vn = g_vuv[i + 1];
    const float v48a = (float)(vi & 1),         v48b = (float)(vn & 1);
    const float v144a = (float)((vi >> 1) & 1), v144b = (float)((vn >> 1) & 1);
    const float v432a = (float)((vi >> 2) & 1), v432b = (float)((vn >> 2) & 1);

    float ph[4], trv[4], f0cv[4];
    #pragma unroll
    for (int r = 0; r < 4; r++) {
        const double jd = (double)(j0 + r);
        const double u = base + (jd + 1.0) * c1 + (jd * (jd + 1.0)) * c2h;
        ph[r] = (float)(u - floor(u));
        trv[r] = g_trans[j0 + r];
        f0cv[r] = af + (bf - af) * ((float)(j0 + r) * (1.0f / 480.0f));
    }

    float4 out;
    float* op = (float*)&out;
    #pragma unroll
    for (int r = 0; r < 4; r++) {
        float acc = 0.0f;
        acc += band_lookup(g_pr48, 48 * 1024, ph[r], trv[r], v48a, v48b);
        acc += band_lookup(g_pr144, 144 * 1024, ph[r], trv[r], v144a, v144b);
        acc += band_lookup(g_pr432, 432 * 1024, ph[r], trv[r], v432a, v432b);
        op[r] = acc * f0cv[r] * (1.0f / 48000.0f);
    }
    *(float4*)(g_p2x + s0) = out;
}

// ---------------- K4: STFT->truncate->ISTFT via FFT512 + packed IFFT256 ----------------
template<int N, int S>
__device__ __forceinline__ void step8(const float2* __restrict__ src, float2* __restrict__ dst,
                                      int t) {
    constexpr int N1 = N / 8;
    constexpr int M = 1024 / N;
    const int p = t / S;
    const int q = t - p * S;

    float2 x[8];
    #pragma unroll
    for (int r = 0; r < 8; r++) x[r] = src[PADI(q + S * (p + r * N1))];

    float2 ea = cadd(x[0], x[4]), eb = csub(x[0], x[4]);
    float2 ec = cadd(x[2], x[6]), ed = csub(x[2], x[6]);
    float2 E0 = cadd(ea, ec), E2 = csub(ea, ec);
    float2 E1 = csub(eb, jmul(ed)), E3 = cadd(eb, jmul(ed));

    float2 oa = cadd(x[1], x[5]), ob = csub(x[1], x[5]);
    float2 oc = cadd(x[3], x[7]), od = csub(x[3], x[7]);
    float2 O0 = cadd(oa, oc), O2 = csub(oa, oc);
    float2 O1 = csub(ob, jmul(od)), O3 = cadd(ob, jmul(od));

    const float C = 0.70710678118654752440f;
    float2 T1 = make_float2(C * (O1.x + O1.y), C * (O1.y - O1.x));
    float2 T2 = make_float2(O2.y, -O2.x);
    float2 T3 = make_float2(C * (O3.y - O3.x), -C * (O3.x + O3.y));

    float2 Y[8];
    Y[0] = cadd(E0, O0); Y[4] = csub(E0, O0);
    Y[1] = cadd(E1, T1); Y[5] = csub(E1, T1);
    Y[2] = cadd(E2, T2); Y[6] = csub(E2, T2);
    Y[3] = cadd(E3, T3); Y[7] = csub(E3, T3);

    if (N == 8) {
        #pragma unroll
        for (int r = 0; r < 8; r++) dst[PADI(q + S * (8 * p + r))] = Y[r];
    } else {
        const float2 w1 = __ldg(&g_tw[p * M]);
        const float2 w2 = cmul(w1, w1);
        const float2 w3 = cmul(w2, w1);
        const float2 w4 = cmul(w2, w2);
        const float2 w5 = cmul(w4, w1);
        const float2 w6 = cmul(w4, w2);
        const float2 w7 = cmul(w4, w3);
        dst[PADI(q + S * (8 * p + 0))] = Y[0];
        dst[PADI(q + S * (8 * p + 1))] = cmul(w1, Y[1]);
        dst[PADI(q + S * (8 * p + 2))] = cmul(w2, Y[2]);
        dst[PADI(q + S * (8 * p + 3))] = cmul(w3, Y[3]);
        dst[PADI(q + S * (8 * p + 4))] = cmul(w4, Y[4]);
        dst[PADI(q + S * (8 * p + 5))] = cmul(w5, Y[5]);
        dst[PADI(q + S * (8 * p + 6))] = cmul(w6, Y[6]);
        dst[PADI(q + S * (8 * p + 7))] = cmul(w7, Y[7]);
    }
}

template<int N, int S>
__device__ __forceinline__ void step4(const float2* __restrict__ src, float2* __restrict__ dst,
                                      int t) {
    constexpr int N1 = N / 4;
    constexpr int M = 1024 / N;
    const int p = t / S;
    const int q = t - p * S;
    float2 a = src[PADI(q + S * p)];
    float2 b = src[PADI(q + S * (p + N1))];
    float2 c = src[PADI(q + S * (p + 2 * N1))];
    float2 d = src[PADI(q + S * (p + 3 * N1))];
    float2 apc = cadd(a, c), amc = csub(a, c);
    float2 bpd = cadd(b, d), jbmd = jmul(csub(b, d));
    float2 Y0 = cadd(apc, bpd);
    float2 Y1 = csub(amc, jbmd);
    float2 Y2 = csub(apc, bpd);
    float2 Y3 = cadd(amc, jbmd);
    if (N == 4) {
        dst[PADI(q + S * (4 * p + 0))] = Y0;
        dst[PADI(q + S * (4 * p + 1))] = Y1;
        dst[PADI(q + S * (4 * p + 2))] = Y2;
        dst[PADI(q + S * (4 * p + 3))] = Y3;
    } else {
        const float2 w1 = __ldg(&g_tw[p * M]);
        const float2 w2 = cmul(w1, w1);
        const float2 w3 = cmul(w2, w1);
        dst[PADI(q + S * (4 * p + 0))] = Y0;
        dst[PADI(q + S * (4 * p + 1))] = cmul(w1, Y1);
        dst[PADI(q + S * (4 * p + 2))] = cmul(w2, Y2);
        dst[PADI(q + S * (4 * p + 3))] = cmul(w3, Y3);
    }
}

#define FPB 4   /* frames per block */

__global__ void __launch_bounds__(64 * FPB) k_fft() {
    __shared__ float2 Ub[FPB][PADSZ];
    __shared__ float2 Vb[FPB][PADSZ];
    const int tid = threadIdx.x;
    const int sub = tid >> 6;
    const int t = tid & 63;
    const int frame = blockIdx.x * FPB + sub;
    const bool valid = (frame < NSTFT);

    float2* U = Ub[sub];
    float2* V = Vb[sub];

    #pragma unroll
    for (int n0 = t; n0 < 512; n0 += 64) {
        float xe = 0.0f, xo = 0.0f;
        if (valid) {
            int ge = frame * HOP2XC - 512 + 2 * n0;
            if (ge >= 0 && ge + 1 < L2X) {
                float2 v = *(const float2*)(g_p2x + ge);
                xe = v.x; xo = v.y;
            } else {
                int go = ge + 1;
                if (ge < 0) ge = -ge;
                if (ge >= L2X) ge = 2 * L2X - 2 - ge;
                if (go < 0) go = -go;
                if (go >= L2X) go = 2 * L2X - 2 - go;
                xe = g_p2x[ge];
                xo = g_p2x[go];
            }
            xe *= g_w1024[2 * n0];
            xo *= g_w1024[2 * n0 + 1];
        }
        U[PADI(n0)] = make_float2(xe, xo);
    }
    __syncthreads();

    // forward 512-pt FFT (3 radix-8 stages): result Z in V
    step8<512, 1>(U, V, t);  __syncthreads();
    step8<64, 8>(V, U, t);   __syncthreads();
    step8<8, 64>(U, V, t);   __syncthreads();

    // unpack real-FFT bins X[0..256] and build conj of irfft-256 packing in U[0..255]
    for (int j = t; j <= 128; j += 64) {
        const float2 Zj = V[PADI(j)];
        const float2 Zmj = V[PADI((512 - j) & 511)];
        float2 E = make_float2(0.5f * (Zj.x + Zmj.x), 0.5f * (Zj.y - Zmj.y));
        float2 O = make_float2(0.5f * (Zj.y + Zmj.y), -0.5f * (Zj.x - Zmj.x));
        float2 Xa = cadd(E, cmul(__ldg(&g_tw[j]), O));
        if (j == 0) {
            const float X0r = Xa.x;
            const float X256r = V[PADI(256)].x;
            U[PADI(0)] = make_float2(0.5f * (X0r + X256r), -0.5f * (X0r - X256r));
        } else {
            const int jp = 256 - j;
            const float2 Zk = V[PADI(jp)];
            const float2 Zmk = V[PADI(256 + j)];
            float2 E2 = make_float2(0.5f * (Zk.x + Zmk.x), 0.5f * (Zk.y - Zmk.y));
            float2 O2 = make_float2(0.5f * (Zk.y + Zmk.y), -0.5f * (Zk.x - Zmk.x));
            float2 Xb = cadd(E2, cmul(__ldg(&g_tw[jp]), O2));

            const float2 t2 = __ldg(&g_tw[2 * j]);
            const float2 tp = make_float2(t2.x, -t2.y);
            const float2 tpn = make_float2(-t2.x, -t2.y);

            float2 S1 = make_float2(Xa.x + Xb.x, Xa.y - Xb.y);
            float2 D1 = make_float2(Xa.x - Xb.x, Xa.y + Xb.y);
            float2 zt = jmul(cmul(tp, D1));
            float2 zj = make_float2(0.5f * (S1.x + zt.x), 0.5f * (S1.y + zt.y));
            U[PADI(j)] = make_float2(zj.x, -zj.y);

            float2 S2 = make_float2(Xb.x + Xa.x, Xb.y - Xa.y);
            float2 D2 = make_float2(Xb.x - Xa.x, Xb.y + Xa.y);
            float2 zt2 = jmul(cmul(tpn, D2));
            float2 zp = make_float2(0.5f * (S2.x + zt2.x), 0.5f * (S2.y + zt2.y));
            U[PADI(jp)] = make_float2(zp.x, -zp.y);
        }
    }
    __syncthreads();

    // 256-pt forward FFT of conj(z) (4 radix-4 stages): result in U
    step4<256, 1>(U, V, t);  __syncthreads();
    step4<64, 4>(V, U, t);   __syncthreads();
    step4<16, 16>(U, V, t);  __syncthreads();
    step4<4, 64>(V, U, t);   __syncthreads();

    if (valid) {
        #pragma unroll
        for (int m = t; m < 256; m += 64) {
            const float2 c = U[PADI(m)];
            float2 o;
            o.x = c.x * (1.0f / 256.0f) * g_w512[2 * m];
            o.y = -c.y * (1.0f / 256.0f) * g_w512[2 * m + 1];
            *(float2*)(g_ybuf + frame * 512 + 2 * m) = o;
        }
    }
}

// ---------------- K5: OLA, 2 samples/thread, float2 loads, env reciprocal table ------
__device__ __forceinline__ float ola_generic(int s) {
    int tlo = (s >= 512) ? (s - 511 + 239) / 240 : 0;
    int thi = s / 240;
    if (thi > NFRAMES) thi = NFRAMES;
    float sig = 0.0f, env = 0.0f;
    for (int t = tlo; t <= thi; t++) {
        const int m = s - 240 * t;
        const float w = g_w512[m];
        sig += g_ybuf[t * 512 + m];
        env += w * w;
    }
    return (env > 1e-11f) ? (sig / env) : 0.0f;
}

__global__ void __launch_bounds__(256) k_ola(float* __restrict__ out) {
    const int idx = blockIdx.x * blockDim.x + threadIdx.x;   // OUTLEN/2 threads
    const int n0 = idx * 2;
    if (n0 >= OUTLEN) return;
    const int s = n0 + 256;                                   // even

    if (s >= 512 && s <= 3932158) {
        // interior: samples s and s+1 share the same frame-term set
        const int thi = s / 240;
        const int r0 = s - 240 * thi;                         // even, 0..238
        const float2 v0 = *(const float2*)(g_ybuf + thi * 512 + r0);
        const float2 v1 = *(const float2*)(g_ybuf + (thi - 1) * 512 + r0 + 240);
        float sig1 = v0.x + v1.x;
        float sig2 = v0.y + v1.y;
        if (r0 <= 30) {
            const float2 v2 = *(const float2*)(g_ybuf + (thi - 2) * 512 + r0 + 480);
            sig1 += v2.x;
            sig2 += v2.y;
        }
        float2 o;
        o.x = sig1 * g_ienv[r0];
        o.y = sig2 * g_ienv[r0 + 1];
        *(float2*)(out + n0) = o;
    } else {
        out[n0] = ola_generic(s);
        if (n0 + 1 < OUTLEN) out[n0 + 1] = ola_generic(s + 1);
    }
}

// ---------------- launcher ----------------
extern "C" void kernel_launch(void* const* d_in, const int* in_sizes, int n_in,
                              void* d_out, int out_size) {
    const float* f0    = (const float*)d_in[0];
    const float* py48  = (const float*)d_in[1];
    const float* py144 = (const float*)d_in[2];
    const float* py432 = (const float*)d_in[3];
    float* out = (float*)d_out;
    (void)in_sizes; (void)n_in; (void)out_size;

    k_init<<<(LEN432 + 255) / 256, 256>>>(f0, py48, py144, py432);
    k_scan1<<<NCHUNK, CHUNKSZ>>>();
    k_scan2<<<1, NCHUNK>>>();
    k_gen<<<L2X / 4 / 256, 256>>>();
    k_fft<<<(NSTFT + FPB - 1) / FPB, 64 * FPB>>>();
    k_ola<<<(OUTLEN / 2 + 255) / 256, 256>>>(out);
}